// round 11
// baseline (speedup 1.0000x reference)
#include <cuda_runtime.h>
#include <cuda_bf16.h>
#include <cuda_fp16.h>
#include <cstdint>

#define NN   50000
#define EE   800000
#define RR   8
#define HH   128
#define NEG  0.2f
#define SCAN_T 1024

// ---------------- scratch (device globals; no runtime allocation) -------------
__device__ __half g_xW16[RR * NN * HH];    // [R,N,H] per-relation transforms (fp16)
__device__ float g_sq[RR * NN];            // xW . q (fp32)
__device__ float g_sk[RR * NN];            // xW . k
__device__ float g_ew[EE];                 // per-edge exp(leaky(alpha)), CSR order
__device__ int   g_rowptr[NN + 1];
__device__ int   g_cursor[NN];
__device__ int   g_edges [EE];             // packed: src | (etype<<16), CSR order
__device__ int   g_etgt  [EE];             // target node per CSR slot
// fp16 activation images (single precision term on the A side)
__device__ __half g_Xf[NN * HH];
__device__ __half g_Hf[NN * HH];           // layer outputs (reused l1 -> l2)
// fp16 hi/lo weight images, [R][N][K] plain layout
__device__ __half g_B1hi[RR * 16384];
__device__ __half g_B1lo[RR * 16384];
__device__ __half g_B2hi[RR * 16384];
__device__ __half g_B2lo[RR * 16384];
__device__ __half g_Blhi[16384];           // final linear (Wl, no transpose)
__device__ __half g_Bllo[16384];

// ---------------- PTX helpers -------------------------------------------------
__device__ __forceinline__ uint32_t smem_u32(const void* p) {
    uint32_t a;
    asm("{ .reg .u64 t; cvta.to.shared.u64 t, %1; cvt.u32.u64 %0, t; }" : "=r"(a) : "l"(p));
    return a;
}
__device__ __forceinline__ void ldsm4(uint32_t* r, uint32_t addr) {
    asm volatile("ldmatrix.sync.aligned.m8n8.x4.shared.b16 {%0,%1,%2,%3}, [%4];"
                 : "=r"(r[0]), "=r"(r[1]), "=r"(r[2]), "=r"(r[3]) : "r"(addr));
}
__device__ __forceinline__ void mma16816(float* c, const uint32_t* a,
                                         uint32_t b0, uint32_t b1) {
    asm volatile(
        "mma.sync.aligned.m16n8k16.row.col.f32.f16.f16.f32 "
        "{%0,%1,%2,%3}, {%4,%5,%6,%7}, {%8,%9}, {%0,%1,%2,%3};"
        : "+f"(c[0]), "+f"(c[1]), "+f"(c[2]), "+f"(c[3])
        : "r"(a[0]), "r"(a[1]), "r"(a[2]), "r"(a[3]), "r"(b0), "r"(b1));
}
__device__ __forceinline__ void split_fp16(float v, __half& hi, __half& lo) {
    hi = __float2half_rn(v);
    lo = __float2half_rn(v - __half2float(hi));
}

// smem geometry
#define ROWB 272                      // padded fp16 row: 136 halves = 272 B
#define BTILE (128 * ROWB)            // 34816 (128 rows)
#define SMEM_TC (3 * BTILE)           // 104448: A(128 rows) + B hi/lo -> 2 blocks/SM
#define F32STRIDE 528                 // fp32 epilogue staging row stride (bytes)

// ---------------- activation conversion: fp32 -> fp16 -------------------------
__global__ void k_convX(const float* __restrict__ X, __half* __restrict__ Xf) {
    int c = blockIdx.x * blockDim.x + threadIdx.x;     // NN*16 chunks of 8
    if (c >= NN * 16) return;
    const float4* p = (const float4*)(X + (size_t)c * 8);
    float4 f0 = p[0], f1 = p[1];
    uint32_t w[4];
    __half2 h;
    h = __floats2half2_rn(f0.x, f0.y); w[0] = *(uint32_t*)&h;
    h = __floats2half2_rn(f0.z, f0.w); w[1] = *(uint32_t*)&h;
    h = __floats2half2_rn(f1.x, f1.y); w[2] = *(uint32_t*)&h;
    h = __floats2half2_rn(f1.z, f1.w); w[3] = *(uint32_t*)&h;
    *(uint4*)(Xf + (size_t)c * 8) = make_uint4(w[0], w[1], w[2], w[3]);
}

// ---------------- weight prep: all weights -> fp16 hi/lo images ---------------
__global__ void k_prep(const float* __restrict__ W1, const float* __restrict__ W2,
                       const float* __restrict__ Wl) {
    int idx = blockIdx.x * blockDim.x + threadIdx.x;
    const int RW = RR * 16384;
    if (idx >= 2 * RW + 16384) return;
    float w;
    __half *dh, *dl;
    int dsti;
    if (idx < 2 * RW) {
        const float* W = (idx < RW) ? W1 : W2;
        int i = (idx < RW) ? idx : idx - RW;
        int r = i >> 14, rem = i & 16383;
        int n = rem >> 7, k = rem & 127;
        w = W[r * 16384 + k * 128 + n];          // transpose: Wt[n][k] = W[k][n]
        dh = (idx < RW) ? g_B1hi : g_B2hi;
        dl = (idx < RW) ? g_B1lo : g_B2lo;
        dsti = r * 16384 + n * 128 + k;
    } else {
        int i = idx - 2 * RW;
        w = Wl[i];                               // B[j][k] = Wl[j][k], no transpose
        dh = g_Blhi; dl = g_Bllo; dsti = i;
    }
    __half hi, lo;
    split_fp16(w, hi, lo);
    dh[dsti] = hi;
    dl[dsti] = lo;
}

// ---------------- CSR build ---------------------------------------------------
__global__ void k_zero_deg() {
    int i = blockIdx.x * blockDim.x + threadIdx.x;
    if (i < NN) g_cursor[i] = 0;
}
__global__ void k_hist(const int* __restrict__ tgt) {
    int e = blockIdx.x * blockDim.x + threadIdx.x;
    if (e < EE) atomicAdd(&g_cursor[tgt[e]], 1);
}
__global__ void __launch_bounds__(SCAN_T) k_scan_one() {
    __shared__ int part[SCAN_T];
    int t = threadIdx.x;
    const int per = (NN + SCAN_T - 1) / SCAN_T;
    int lo = t * per;
    int hi = lo + per; if (hi > NN) hi = NN;
    int s = 0;
    for (int i = lo; i < hi; i++) s += g_cursor[i];
    part[t] = s;
    __syncthreads();
    for (int off = 1; off < SCAN_T; off <<= 1) {
        int v = (t >= off) ? part[t - off] : 0;
        __syncthreads();
        part[t] += v;
        __syncthreads();
    }
    int run = (t > 0) ? part[t - 1] : 0;
    for (int i = lo; i < hi; i++) {
        int d = g_cursor[i];
        g_rowptr[i] = run;
        g_cursor[i] = run;
        run += d;
    }
    if (t == 0) g_rowptr[NN] = EE;
}
__global__ void k_fill(const int* __restrict__ src, const int* __restrict__ tgt,
                       const int* __restrict__ etype) {
    int e = blockIdx.x * blockDim.x + threadIdx.x;
    if (e < EE) {
        int t = tgt[e];
        int pos = atomicAdd(&g_cursor[t], 1);
        g_edges[pos] = src[e] | (etype[e] << 16);
        g_etgt[pos]  = t;
    }
}

// ---------------- per-edge attention scores (edge-parallel) -------------------
__global__ void k_escore(const float* __restrict__ sq, const float* __restrict__ sk) {
    int j = blockIdx.x * blockDim.x + threadIdx.x;
    if (j >= EE) return;
    int p = g_edges[j];
    int s = p & 0xffff, et = p >> 16;
    int t = g_etgt[j];
    float v = sq[et * NN + t] + sk[et * NN + s];
    v = v > 0.f ? v : NEG * v;
    g_ew[j] = __expf(v);      // shift-invariant: no max-subtract needed
}

// ---------------- HMMA GEMM (BM=128, BN=128, warp tile 64x32, 2-term) ---------
// C = A(fp16) @ (Bhi + Blo)^T.
// FINAL=0: Y16[r] = fp16(A @ B[r]^T), fused sq/sk scores.
// FINAL=1: Yf = A @ Wl^T + bias (fp32, straight to d_out).
template <bool FINAL>
__global__ void __launch_bounds__(256, 2)
k_gemm_tc(const __half* __restrict__ Ag,
          const __half* __restrict__ Bhi, const __half* __restrict__ Blo,
          __half* __restrict__ Y16, float* __restrict__ Yf,
          float* __restrict__ sq, float* __restrict__ sk,
          const float* __restrict__ qv, const float* __restrict__ kv,
          const float* __restrict__ bias)
{
    extern __shared__ __align__(16) char dynsm[];
    char* sA   = dynsm;                 // 128 rows
    char* sBhi = dynsm + BTILE;
    char* sBlo = dynsm + 2 * BTILE;

    __shared__ float s_q[128], s_k[128], s_b[128];
    __shared__ float s_redq[512], s_redk[512];

    const int tid  = threadIdx.x;
    const int wid  = tid >> 5;
    const int lane = tid & 31;
    const int mw   = wid & 1;          // m offset 64*mw
    const int nw   = wid >> 1;         // n offset 32*nw
    const int r    = blockIdx.y;
    const int row0 = blockIdx.x * 128;

    if (!FINAL) {
        if (tid < 128) { s_q[tid] = qv[tid]; s_k[tid] = kv[tid]; }
    } else {
        if (tid < 128) s_b[tid] = bias[tid];
    }

    // --- B copy gmem [N=128][K=128] -> smem padded rows (hi and lo) ---
    {
        const uint4* gh = (const uint4*)(Bhi + (size_t)r * 16384);
        const uint4* gl = (const uint4*)(Blo + (size_t)r * 16384);
#pragma unroll
        for (int i = 0; i < 8; i++) {
            int c = tid + 256 * i;
            int row = c >> 4, c16 = c & 15;
            uint32_t off = row * ROWB + c16 * 16;
            *(uint4*)(sBhi + off) = gh[c];
            *(uint4*)(sBlo + off) = gl[c];
        }
    }
    // --- A copy: fp16 rows -> smem padded (128 rows) ---
#pragma unroll
    for (int i = 0; i < 8; i++) {
        int c = tid + 256 * i;               // 2048 chunks of 8 halves
        int row = c >> 4, seg = c & 15;
        int grow = row0 + row;
        uint4 v = make_uint4(0, 0, 0, 0);
        if (grow < NN)
            v = *(const uint4*)(Ag + (size_t)grow * HH + seg * 8);
        *(uint4*)(sA + row * ROWB + seg * 16) = v;
    }
    __syncthreads();

    // --- mainloop: c += A*Bhi + A*Blo ---
    float acc[4][4][4];
#pragma unroll
    for (int mt = 0; mt < 4; mt++)
#pragma unroll
        for (int nt = 0; nt < 4; nt++)
#pragma unroll
            for (int j = 0; j < 4; j++) acc[mt][nt][j] = 0.f;

    const uint32_t aB   = smem_u32(sA);
    const uint32_t bHiB = smem_u32(sBhi), bLoB = smem_u32(sBlo);
    const int arow  = mw * 64 + (lane & 7) + ((lane >> 3) & 1) * 8;
    const int akcol = (lane >> 4) * 8;
    const uint32_t aoff = (uint32_t)(arow * ROWB + akcol * 2);
    const int brow  = nw * 32 + (lane & 7) + ((lane >> 4) & 1) * 8;
    const int bkcol = ((lane >> 3) & 1) * 8;
    const uint32_t boff = (uint32_t)(brow * ROWB + bkcol * 2);

#pragma unroll
    for (int ks = 0; ks < 8; ks++) {
        const uint32_t ko = ks * 32;
        uint32_t a[4][4], b[2][4];
#pragma unroll
        for (int mt = 0; mt < 4; mt++)
            ldsm4(a[mt], aB + aoff + mt * 16 * ROWB + ko);
        // hi image
        ldsm4(b[0], bHiB + boff + ko);
        ldsm4(b[1], bHiB + boff + 16 * ROWB + ko);
#pragma unroll
        for (int mt = 0; mt < 4; mt++)
#pragma unroll
            for (int p = 0; p < 2; p++) {
                mma16816(acc[mt][2*p],   a[mt], b[p][0], b[p][1]);
                mma16816(acc[mt][2*p+1], a[mt], b[p][2], b[p][3]);
            }
        // lo image
        ldsm4(b[0], bLoB + boff + ko);
        ldsm4(b[1], bLoB + boff + 16 * ROWB + ko);
#pragma unroll
        for (int mt = 0; mt < 4; mt++)
#pragma unroll
            for (int p = 0; p < 2; p++) {
                mma16816(acc[mt][2*p],   a[mt], b[p][0], b[p][1]);
                mma16816(acc[mt][2*p+1], a[mt], b[p][2], b[p][3]);
            }
    }
    __syncthreads();    // done reading sA/sB; reuse sA as staging

    if (!FINAL) {
        float pq[8], pk[8];
#pragma unroll
        for (int j = 0; j < 8; j++) { pq[j] = 0.f; pk[j] = 0.f; }
#pragma unroll
        for (int mt = 0; mt < 4; mt++) {
            const int lrow = mw * 64 + mt * 16 + (lane >> 2);
#pragma unroll
            for (int nt = 0; nt < 4; nt++) {
                const int col = nw * 32 + nt * 8 + (lane & 3) * 2;
                float c0 = acc[mt][nt][0], c1 = acc[mt][nt][1];
                float c2 = acc[mt][nt][2], c3 = acc[mt][nt][3];
                float q0 = s_q[col], q1 = s_q[col + 1];
                float k0 = s_k[col], k1 = s_k[col + 1];
                pq[mt*2]   += c0 * q0 + c1 * q1;
                pq[mt*2+1] += c2 * q0 + c3 * q1;
                pk[mt*2]   += c0 * k0 + c1 * k1;
                pk[mt*2+1] += c2 * k0 + c3 * k1;
                *(__half2*)(sA + lrow * ROWB + col * 2)       = __floats2half2_rn(c0, c1);
                *(__half2*)(sA + (lrow + 8) * ROWB + col * 2) = __floats2half2_rn(c2, c3);
            }
        }
#pragma unroll
        for (int off = 1; off <= 2; off <<= 1)
#pragma unroll
            for (int j = 0; j < 8; j++) {
                pq[j] += __shfl_xor_sync(0xffffffffu, pq[j], off);
                pk[j] += __shfl_xor_sync(0xffffffffu, pk[j], off);
            }
        if ((lane & 3) == 0) {
#pragma unroll
            for (int mt = 0; mt < 4; mt++) {
                int lrow = mw * 64 + mt * 16 + (lane >> 2);
                s_redq[nw * 128 + lrow]     = pq[mt*2];
                s_redq[nw * 128 + lrow + 8] = pq[mt*2+1];
                s_redk[nw * 128 + lrow]     = pk[mt*2];
                s_redk[nw * 128 + lrow + 8] = pk[mt*2+1];
            }
        }
        __syncthreads();
        if (tid < 128) {
            int grow = row0 + tid;
            if (grow < NN) {
                sq[r * NN + grow] = s_redq[tid] + s_redq[128 + tid] + s_redq[256 + tid] + s_redq[384 + tid];
                sk[r * NN + grow] = s_redk[tid] + s_redk[128 + tid] + s_redk[256 + tid] + s_redk[384 + tid];
            }
        }
        // --- coalesced bulk copy: 128 rows x 128 halves ---
#pragma unroll
        for (int i = 0; i < 8; i++) {
            int c = tid + 256 * i;
            int row = c >> 4, seg = c & 15;
            int grow = row0 + row;
            if (grow < NN)
                *(uint4*)&Y16[((size_t)r * NN + grow) * HH + seg * 8] =
                    *(const uint4*)(sA + row * ROWB + seg * 16);
        }
    } else {
        // --- fp32 staging with bias (128 rows x 528B = 67.6KB < 104KB), copy ---
#pragma unroll
        for (int mt = 0; mt < 4; mt++) {
            const int lrow = mw * 64 + mt * 16 + (lane >> 2);
#pragma unroll
            for (int nt = 0; nt < 4; nt++) {
                const int col = nw * 32 + nt * 8 + (lane & 3) * 2;
                float b0 = s_b[col], b1 = s_b[col + 1];
                *(float2*)(sA + lrow * F32STRIDE + col * 4) =
                    make_float2(acc[mt][nt][0] + b0, acc[mt][nt][1] + b1);
                *(float2*)(sA + (lrow + 8) * F32STRIDE + col * 4) =
                    make_float2(acc[mt][nt][2] + b0, acc[mt][nt][3] + b1);
            }
        }
        __syncthreads();
#pragma unroll
        for (int i = 0; i < 16; i++) {
            int c = tid + 256 * i;               // 4096 uint4
            int row = c >> 5, seg = c & 31;
            int grow = row0 + row;
            if (grow < NN)
                *(uint4*)&Yf[(size_t)grow * HH + seg * 4] =
                    *(const uint4*)(sA + row * F32STRIDE + seg * 16);
        }
    }
}

// ---------------- aggregation (warp per node, precomputed edge weights) -------
// den: coalesced sum of ew over the segment.
// gather: half-warps alternate edges; per lane 1 broadcast wt, 1 broadcast idx,
// one 16B row slice, 8 FMAs. No shfl in the hot loop -> deep MLP.
__global__ void __launch_bounds__(256)
k_agg(const __half* __restrict__ xW, const float* __restrict__ bias,
      __half* __restrict__ outH)
{
    int warp = (blockIdx.x * blockDim.x + threadIdx.x) >> 5;
    int lane = threadIdx.x & 31;
    if (warp >= NN) return;
    const int n     = warp;
    const int start = g_rowptr[n];
    const int end   = g_rowptr[n + 1];

    // den: coalesced
    float den = 0.f;
    for (int j = start + lane; j < end; j += 32) den += g_ew[j];
#pragma unroll
    for (int off = 16; off; off >>= 1)
        den += __shfl_xor_sync(0xffffffffu, den, off);

    // gather
    const int half16 = lane >> 4;
    const int c8     = (lane & 15) * 8;
    float acc[8] = {0.f, 0.f, 0.f, 0.f, 0.f, 0.f, 0.f, 0.f};
    for (int j = start + half16; j < end; j += 2) {
        float wt = g_ew[j];
        int   pt = g_edges[j];
        int st = pt & 0xffff, rt = pt >> 16;
        uint4 raw = *(const uint4*)&xW[((size_t)rt * NN + st) * HH + c8];
        const __half2* hp = (const __half2*)&raw;
#pragma unroll
        for (int k = 0; k < 4; k++) {
            float2 f = __half22float2(hp[k]);
            acc[2*k]   += wt * f.x;
            acc[2*k+1] += wt * f.y;
        }
    }
#pragma unroll
    for (int j = 0; j < 8; j++)
        acc[j] += __shfl_xor_sync(0xffffffffu, acc[j], 16);

    if (lane < 16) {
        float inv = 1.f / (den + 1e-16f);
        float4 b0 = *(const float4*)&bias[lane * 8];
        float4 b1 = *(const float4*)&bias[lane * 8 + 4];
        float o[8];
        o[0] = fmaxf(acc[0] * inv + b0.x, 0.f);
        o[1] = fmaxf(acc[1] * inv + b0.y, 0.f);
        o[2] = fmaxf(acc[2] * inv + b0.z, 0.f);
        o[3] = fmaxf(acc[3] * inv + b0.w, 0.f);
        o[4] = fmaxf(acc[4] * inv + b1.x, 0.f);
        o[5] = fmaxf(acc[5] * inv + b1.y, 0.f);
        o[6] = fmaxf(acc[6] * inv + b1.z, 0.f);
        o[7] = fmaxf(acc[7] * inv + b1.w, 0.f);
        uint32_t hw[4];
        __half2 h;
        h = __floats2half2_rn(o[0], o[1]); hw[0] = *(uint32_t*)&h;
        h = __floats2half2_rn(o[2], o[3]); hw[1] = *(uint32_t*)&h;
        h = __floats2half2_rn(o[4], o[5]); hw[2] = *(uint32_t*)&h;
        h = __floats2half2_rn(o[6], o[7]); hw[3] = *(uint32_t*)&h;
        *(uint4*)&outH[(size_t)n * HH + lane * 8] = make_uint4(hw[0], hw[1], hw[2], hw[3]);
    }
}

// ---------------- launch ------------------------------------------------------
extern "C" void kernel_launch(void* const* d_in, const int* in_sizes, int n_in,
                              void* d_out, int out_size)
{
    const float* x  = (const float*)d_in[0];
    const int*   ei = (const int*)  d_in[1];
    const int*   et = (const int*)  d_in[2];
    const float* W1 = (const float*)d_in[4];
    const float* q1 = (const float*)d_in[5];
    const float* k1 = (const float*)d_in[6];
    const float* b1 = (const float*)d_in[7];
    const float* W2 = (const float*)d_in[8];
    const float* q2 = (const float*)d_in[9];
    const float* k2 = (const float*)d_in[10];
    const float* b2 = (const float*)d_in[11];
    const float* Wl = (const float*)d_in[12];
    const float* bl = (const float*)d_in[13];
    float* out = (float*)d_out;

    const int* srcp = ei;
    const int* tgtp = ei + EE;

    float *psq, *psk;
    __half *pxW, *pXf, *pHf;
    __half *pB1h, *pB1l, *pB2h, *pB2l, *pBlh, *pBll;
    cudaGetSymbolAddress((void**)&pxW, g_xW16);
    cudaGetSymbolAddress((void**)&psq, g_sq);
    cudaGetSymbolAddress((void**)&psk, g_sk);
    cudaGetSymbolAddress((void**)&pXf, g_Xf);
    cudaGetSymbolAddress((void**)&pHf, g_Hf);
    cudaGetSymbolAddress((void**)&pB1h, g_B1hi);
    cudaGetSymbolAddress((void**)&pB1l, g_B1lo);
    cudaGetSymbolAddress((void**)&pB2h, g_B2hi);
    cudaGetSymbolAddress((void**)&pB2l, g_B2lo);
    cudaGetSymbolAddress((void**)&pBlh, g_Blhi);
    cudaGetSymbolAddress((void**)&pBll, g_Bllo);

    cudaFuncSetAttribute(k_gemm_tc<false>, cudaFuncAttributeMaxDynamicSharedMemorySize, SMEM_TC);
    cudaFuncSetAttribute(k_gemm_tc<true>,  cudaFuncAttributeMaxDynamicSharedMemorySize, SMEM_TC);

    const int GT128 = (NN + 127) / 128;        // 391
    dim3 tc_grid(GT128, RR);
    const int agg_blocks = (NN * 32 + 255) / 256;
    const int EB = (EE + 255) / 256;

    // Launch order keeps k_gemm_tc (layer 1) as the 4th launch -> ncu capture.
    k_convX<<<(NN * 16 + 255) / 256, 256>>>(x, pXf);
    k_prep<<<((2 * RR + 1) * 16384 + 255) / 256, 256>>>(W1, W2, Wl);
    k_zero_deg<<<(NN + 255) / 256, 256>>>();
    k_gemm_tc<false><<<tc_grid, 256, SMEM_TC>>>(pXf, pB1h, pB1l, pxW, nullptr,
                                                psq, psk, q1, k1, nullptr);   // 4th
    k_hist<<<EB, 256>>>(tgtp);
    k_scan_one<<<1, SCAN_T>>>();
    k_fill<<<EB, 256>>>(srcp, tgtp, et);

    // Layer 1 attention
    k_escore<<<EB, 256>>>(psq, psk);
    k_agg<<<agg_blocks, 256>>>(pxW, b1, pHf);

    // Layer 2
    k_gemm_tc<false><<<tc_grid, 256, SMEM_TC>>>(pHf, pB2h, pB2l, pxW, nullptr,
                                                psq, psk, q2, k2, nullptr);
    k_escore<<<EB, 256>>>(psq, psk);
    k_agg<<<agg_blocks, 256>>>(pxW, b2, pHf);

    // Final linear (h @ Wl^T + bl) straight into d_out
    k_gemm_tc<true><<<dim3(GT128, 1), 256, SMEM_TC>>>(pHf, pBlh, pBll, nullptr, out,
                                                      nullptr, nullptr, nullptr, nullptr, bl);
    (void)in_sizes; (void)n_in; (void)out_size;
}

// round 13
// speedup vs baseline: 1.0369x; 1.0369x over previous
#include <cuda_runtime.h>
#include <cuda_bf16.h>
#include <cuda_fp16.h>
#include <cstdint>

#define NN   50000
#define EE   800000
#define RR   8
#define HH   128
#define NEG  0.2f
#define SCAN_T 1024

// ---------------- scratch (device globals; no runtime allocation) -------------
__device__ __half g_xW16[RR * NN * HH];    // [R,N,H] per-relation transforms (fp16)
__device__ float g_sq[RR * NN];            // xW . q (fp32)
__device__ float g_sk[RR * NN];            // xW . k
__device__ int   g_rowptr[NN + 1];
__device__ int   g_cursor[NN];
__device__ int   g_edges [EE];             // packed: src | (etype<<16), CSR order
// fp16 activation images (single precision term on the A side)
__device__ __half g_Xf[NN * HH];
__device__ __half g_Hf[NN * HH];           // layer outputs (reused l1 -> l2)
// fp16 hi/lo weight images, [R][N][K] plain layout
__device__ __half g_B1hi[RR * 16384];
__device__ __half g_B1lo[RR * 16384];
__device__ __half g_B2hi[RR * 16384];
__device__ __half g_B2lo[RR * 16384];
__device__ __half g_Blhi[16384];           // final linear (Wl, no transpose)
__device__ __half g_Bllo[16384];

// ---------------- PTX helpers -------------------------------------------------
__device__ __forceinline__ uint32_t smem_u32(const void* p) {
    uint32_t a;
    asm("{ .reg .u64 t; cvta.to.shared.u64 t, %1; cvt.u32.u64 %0, t; }" : "=r"(a) : "l"(p));
    return a;
}
__device__ __forceinline__ void ldsm4(uint32_t* r, uint32_t addr) {
    asm volatile("ldmatrix.sync.aligned.m8n8.x4.shared.b16 {%0,%1,%2,%3}, [%4];"
                 : "=r"(r[0]), "=r"(r[1]), "=r"(r[2]), "=r"(r[3]) : "r"(addr));
}
__device__ __forceinline__ void mma16816(float* c, const uint32_t* a,
                                         uint32_t b0, uint32_t b1) {
    asm volatile(
        "mma.sync.aligned.m16n8k16.row.col.f32.f16.f16.f32 "
        "{%0,%1,%2,%3}, {%4,%5,%6,%7}, {%8,%9}, {%0,%1,%2,%3};"
        : "+f"(c[0]), "+f"(c[1]), "+f"(c[2]), "+f"(c[3])
        : "r"(a[0]), "r"(a[1]), "r"(a[2]), "r"(a[3]), "r"(b0), "r"(b1));
}
__device__ __forceinline__ void split_fp16(float v, __half& hi, __half& lo) {
    hi = __float2half_rn(v);
    lo = __float2half_rn(v - __half2float(hi));
}

// smem geometry
#define ROWB 272                      // padded fp16 row: 136 halves = 272 B
#define BTILE (128 * ROWB)            // 34816 (128 rows)
#define SMEM_TC (3 * BTILE)           // 104448: A(128 rows) + B hi/lo -> 2 blocks/SM
#define F32STRIDE 528                 // fp32 epilogue staging row stride (bytes)

// ---------------- activation conversion + degree zero -------------------------
__global__ void k_convX(const float* __restrict__ X, __half* __restrict__ Xf) {
    int c = blockIdx.x * blockDim.x + threadIdx.x;     // NN*16 chunks of 8
    if (c < NN) g_cursor[c] = 0;                       // folded zero_deg
    if (c >= NN * 16) return;
    const float4* p = (const float4*)(X + (size_t)c * 8);
    float4 f0 = p[0], f1 = p[1];
    uint32_t w[4];
    __half2 h;
    h = __floats2half2_rn(f0.x, f0.y); w[0] = *(uint32_t*)&h;
    h = __floats2half2_rn(f0.z, f0.w); w[1] = *(uint32_t*)&h;
    h = __floats2half2_rn(f1.x, f1.y); w[2] = *(uint32_t*)&h;
    h = __floats2half2_rn(f1.z, f1.w); w[3] = *(uint32_t*)&h;
    *(uint4*)(Xf + (size_t)c * 8) = make_uint4(w[0], w[1], w[2], w[3]);
}

// ---------------- weight prep: all weights -> fp16 hi/lo images ---------------
__global__ void k_prep(const float* __restrict__ W1, const float* __restrict__ W2,
                       const float* __restrict__ Wl) {
    int idx = blockIdx.x * blockDim.x + threadIdx.x;
    const int RW = RR * 16384;
    if (idx >= 2 * RW + 16384) return;
    float w;
    __half *dh, *dl;
    int dsti;
    if (idx < 2 * RW) {
        const float* W = (idx < RW) ? W1 : W2;
        int i = (idx < RW) ? idx : idx - RW;
        int r = i >> 14, rem = i & 16383;
        int n = rem >> 7, k = rem & 127;
        w = W[r * 16384 + k * 128 + n];          // transpose: Wt[n][k] = W[k][n]
        dh = (idx < RW) ? g_B1hi : g_B2hi;
        dl = (idx < RW) ? g_B1lo : g_B2lo;
        dsti = r * 16384 + n * 128 + k;
    } else {
        int i = idx - 2 * RW;
        w = Wl[i];                               // B[j][k] = Wl[j][k], no transpose
        dh = g_Blhi; dl = g_Bllo; dsti = i;
    }
    __half hi, lo;
    split_fp16(w, hi, lo);
    dh[dsti] = hi;
    dl[dsti] = lo;
}

// ---------------- CSR build ---------------------------------------------------
__global__ void k_hist(const int* __restrict__ tgt) {
    int e = blockIdx.x * blockDim.x + threadIdx.x;
    if (e < EE) atomicAdd(&g_cursor[tgt[e]], 1);
}
__global__ void __launch_bounds__(SCAN_T) k_scan_one() {
    __shared__ int part[SCAN_T];
    int t = threadIdx.x;
    const int per = (NN + SCAN_T - 1) / SCAN_T;
    int lo = t * per;
    int hi = lo + per; if (hi > NN) hi = NN;
    int s = 0;
    for (int i = lo; i < hi; i++) s += g_cursor[i];
    part[t] = s;
    __syncthreads();
    for (int off = 1; off < SCAN_T; off <<= 1) {
        int v = (t >= off) ? part[t - off] : 0;
        __syncthreads();
        part[t] += v;
        __syncthreads();
    }
    int run = (t > 0) ? part[t - 1] : 0;
    for (int i = lo; i < hi; i++) {
        int d = g_cursor[i];
        g_rowptr[i] = run;
        g_cursor[i] = run;
        run += d;
    }
    if (t == 0) g_rowptr[NN] = EE;
}
__global__ void k_fill(const int* __restrict__ src, const int* __restrict__ tgt,
                       const int* __restrict__ etype) {
    int e = blockIdx.x * blockDim.x + threadIdx.x;
    if (e < EE) {
        int t = tgt[e];
        int pos = atomicAdd(&g_cursor[t], 1);
        g_edges[pos] = src[e] | (etype[e] << 16);
    }
}

// ---------------- HMMA GEMM (BM=128, BN=128, warp tile 64x32, 2-term) ---------
// C = A(fp16) @ (Bhi + Blo)^T.
// FINAL=0: Y16[r] = fp16(A @ B[r]^T), fused sq/sk scores.
// FINAL=1: Yf = A @ Wl^T + bias (fp32, straight to d_out).
template <bool FINAL>
__global__ void __launch_bounds__(256, 2)
k_gemm_tc(const __half* __restrict__ Ag,
          const __half* __restrict__ Bhi, const __half* __restrict__ Blo,
          __half* __restrict__ Y16, float* __restrict__ Yf,
          float* __restrict__ sq, float* __restrict__ sk,
          const float* __restrict__ qv, const float* __restrict__ kv,
          const float* __restrict__ bias)
{
    extern __shared__ __align__(16) char dynsm[];
    char* sA   = dynsm;                 // 128 rows
    char* sBhi = dynsm + BTILE;
    char* sBlo = dynsm + 2 * BTILE;

    __shared__ float s_q[128], s_k[128], s_b[128];
    __shared__ float s_redq[512], s_redk[512];

    const int tid  = threadIdx.x;
    const int wid  = tid >> 5;
    const int lane = tid & 31;
    const int mw   = wid & 1;          // m offset 64*mw
    const int nw   = wid >> 1;         // n offset 32*nw
    const int r    = blockIdx.y;
    const int row0 = blockIdx.x * 128;

    if (!FINAL) {
        if (tid < 128) { s_q[tid] = qv[tid]; s_k[tid] = kv[tid]; }
    } else {
        if (tid < 128) s_b[tid] = bias[tid];
    }

    // --- B copy gmem [N=128][K=128] -> smem padded rows (hi and lo) ---
    {
        const uint4* gh = (const uint4*)(Bhi + (size_t)r * 16384);
        const uint4* gl = (const uint4*)(Blo + (size_t)r * 16384);
#pragma unroll
        for (int i = 0; i < 8; i++) {
            int c = tid + 256 * i;
            int row = c >> 4, c16 = c & 15;
            uint32_t off = row * ROWB + c16 * 16;
            *(uint4*)(sBhi + off) = gh[c];
            *(uint4*)(sBlo + off) = gl[c];
        }
    }
    // --- A copy: fp16 rows -> smem padded (128 rows) ---
#pragma unroll
    for (int i = 0; i < 8; i++) {
        int c = tid + 256 * i;               // 2048 chunks of 8 halves
        int row = c >> 4, seg = c & 15;
        int grow = row0 + row;
        uint4 v = make_uint4(0, 0, 0, 0);
        if (grow < NN)
            v = *(const uint4*)(Ag + (size_t)grow * HH + seg * 8);
        *(uint4*)(sA + row * ROWB + seg * 16) = v;
    }
    __syncthreads();

    // --- mainloop: c += A*Bhi + A*Blo ---
    float acc[4][4][4];
#pragma unroll
    for (int mt = 0; mt < 4; mt++)
#pragma unroll
        for (int nt = 0; nt < 4; nt++)
#pragma unroll
            for (int j = 0; j < 4; j++) acc[mt][nt][j] = 0.f;

    const uint32_t aB   = smem_u32(sA);
    const uint32_t bHiB = smem_u32(sBhi), bLoB = smem_u32(sBlo);
    const int arow  = mw * 64 + (lane & 7) + ((lane >> 3) & 1) * 8;
    const int akcol = (lane >> 4) * 8;
    const uint32_t aoff = (uint32_t)(arow * ROWB + akcol * 2);
    const int brow  = nw * 32 + (lane & 7) + ((lane >> 4) & 1) * 8;
    const int bkcol = ((lane >> 3) & 1) * 8;
    const uint32_t boff = (uint32_t)(brow * ROWB + bkcol * 2);

#pragma unroll
    for (int ks = 0; ks < 8; ks++) {
        const uint32_t ko = ks * 32;
        uint32_t a[4][4], b[2][4];
#pragma unroll
        for (int mt = 0; mt < 4; mt++)
            ldsm4(a[mt], aB + aoff + mt * 16 * ROWB + ko);
        // hi image
        ldsm4(b[0], bHiB + boff + ko);
        ldsm4(b[1], bHiB + boff + 16 * ROWB + ko);
#pragma unroll
        for (int mt = 0; mt < 4; mt++)
#pragma unroll
            for (int p = 0; p < 2; p++) {
                mma16816(acc[mt][2*p],   a[mt], b[p][0], b[p][1]);
                mma16816(acc[mt][2*p+1], a[mt], b[p][2], b[p][3]);
            }
        // lo image
        ldsm4(b[0], bLoB + boff + ko);
        ldsm4(b[1], bLoB + boff + 16 * ROWB + ko);
#pragma unroll
        for (int mt = 0; mt < 4; mt++)
#pragma unroll
            for (int p = 0; p < 2; p++) {
                mma16816(acc[mt][2*p],   a[mt], b[p][0], b[p][1]);
                mma16816(acc[mt][2*p+1], a[mt], b[p][2], b[p][3]);
            }
    }
    __syncthreads();    // done reading sA/sB; reuse sA as staging

    if (!FINAL) {
        float pq[8], pk[8];
#pragma unroll
        for (int j = 0; j < 8; j++) { pq[j] = 0.f; pk[j] = 0.f; }
#pragma unroll
        for (int mt = 0; mt < 4; mt++) {
            const int lrow = mw * 64 + mt * 16 + (lane >> 2);
#pragma unroll
            for (int nt = 0; nt < 4; nt++) {
                const int col = nw * 32 + nt * 8 + (lane & 3) * 2;
                float c0 = acc[mt][nt][0], c1 = acc[mt][nt][1];
                float c2 = acc[mt][nt][2], c3 = acc[mt][nt][3];
                float q0 = s_q[col], q1 = s_q[col + 1];
                float k0 = s_k[col], k1 = s_k[col + 1];
                pq[mt*2]   += c0 * q0 + c1 * q1;
                pq[mt*2+1] += c2 * q0 + c3 * q1;
                pk[mt*2]   += c0 * k0 + c1 * k1;
                pk[mt*2+1] += c2 * k0 + c3 * k1;
                *(__half2*)(sA + lrow * ROWB + col * 2)       = __floats2half2_rn(c0, c1);
                *(__half2*)(sA + (lrow + 8) * ROWB + col * 2) = __floats2half2_rn(c2, c3);
            }
        }
#pragma unroll
        for (int off = 1; off <= 2; off <<= 1)
#pragma unroll
            for (int j = 0; j < 8; j++) {
                pq[j] += __shfl_xor_sync(0xffffffffu, pq[j], off);
                pk[j] += __shfl_xor_sync(0xffffffffu, pk[j], off);
            }
        if ((lane & 3) == 0) {
#pragma unroll
            for (int mt = 0; mt < 4; mt++) {
                int lrow = mw * 64 + mt * 16 + (lane >> 2);
                s_redq[nw * 128 + lrow]     = pq[mt*2];
                s_redq[nw * 128 + lrow + 8] = pq[mt*2+1];
                s_redk[nw * 128 + lrow]     = pk[mt*2];
                s_redk[nw * 128 + lrow + 8] = pk[mt*2+1];
            }
        }
        __syncthreads();
        if (tid < 128) {
            int grow = row0 + tid;
            if (grow < NN) {
                sq[r * NN + grow] = s_redq[tid] + s_redq[128 + tid] + s_redq[256 + tid] + s_redq[384 + tid];
                sk[r * NN + grow] = s_redk[tid] + s_redk[128 + tid] + s_redk[256 + tid] + s_redk[384 + tid];
            }
        }
        // --- coalesced bulk copy: 128 rows x 128 halves ---
#pragma unroll
        for (int i = 0; i < 8; i++) {
            int c = tid + 256 * i;
            int row = c >> 4, seg = c & 15;
            int grow = row0 + row;
            if (grow < NN)
                *(uint4*)&Y16[((size_t)r * NN + grow) * HH + seg * 8] =
                    *(const uint4*)(sA + row * ROWB + seg * 16);
        }
    } else {
        // --- fp32 staging with bias (128 rows x 528B = 67.6KB < 104KB), copy ---
#pragma unroll
        for (int mt = 0; mt < 4; mt++) {
            const int lrow = mw * 64 + mt * 16 + (lane >> 2);
#pragma unroll
            for (int nt = 0; nt < 4; nt++) {
                const int col = nw * 32 + nt * 8 + (lane & 3) * 2;
                float b0 = s_b[col], b1 = s_b[col + 1];
                *(float2*)(sA + lrow * F32STRIDE + col * 4) =
                    make_float2(acc[mt][nt][0] + b0, acc[mt][nt][1] + b1);
                *(float2*)(sA + (lrow + 8) * F32STRIDE + col * 4) =
                    make_float2(acc[mt][nt][2] + b0, acc[mt][nt][3] + b1);
            }
        }
        __syncthreads();
#pragma unroll
        for (int i = 0; i < 16; i++) {
            int c = tid + 256 * i;               // 4096 uint4
            int row = c >> 5, seg = c & 31;
            int grow = row0 + row;
            if (grow < NN)
                *(uint4*)&Yf[(size_t)grow * HH + seg * 4] =
                    *(const uint4*)(sA + row * F32STRIDE + seg * 16);
        }
    }
}

// ---------------- single-pass softmax + aggregation (warp per node) -----------
// Scores computed in-warp per 32-edge batch (hidden under gather latency).
// Gather: 4 edges in flight (2 pairs x half-warps), loads issued before FMAs.
__global__ void __launch_bounds__(256)
k_agg(const __half* __restrict__ xW, const float* __restrict__ sq,
      const float* __restrict__ sk, const float* __restrict__ bias,
      __half* __restrict__ outH)
{
    int warp = (blockIdx.x * blockDim.x + threadIdx.x) >> 5;
    int lane = threadIdx.x & 31;
    if (warp >= NN) return;
    const int n     = warp;
    const int start = g_rowptr[n];
    const int end   = g_rowptr[n + 1];

    float sqv = (lane < RR) ? sq[lane * NN + n] : 0.f;

    const int half16 = lane >> 4;           // which edge of each pair
    const int c8     = (lane & 15) * 8;     // 8-half column group

    float acc[8] = {0.f, 0.f, 0.f, 0.f, 0.f, 0.f, 0.f, 0.f};
    float den = 0.f;
    for (int j0 = start; j0 < end; j0 += 32) {
        int j = j0 + lane;
        int p = (j < end) ? g_edges[j] : 0;
        int s = p & 0xffff, et = p >> 16;
        float v = __shfl_sync(0xffffffffu, sqv, et) + sk[et * NN + s];
        v = v > 0.f ? v : NEG * v;
        float w = (j < end) ? __expf(v) : 0.f;     // shift-invariant softmax
        den += w;
        int cnt = min(32, end - j0);
        for (int t = 0; t < cnt; t += 4) {
            int ia = t + half16;
            int ib = t + 2 + half16;
            int iac = (ia < cnt) ? ia : cnt - 1;
            int ibc = (ib < cnt) ? ib : cnt - 1;
            float wa = __shfl_sync(0xffffffffu, w, iac);
            int   pa = __shfl_sync(0xffffffffu, p, iac);
            float wb = __shfl_sync(0xffffffffu, w, ibc);
            int   pb = __shfl_sync(0xffffffffu, p, ibc);
            if (ia >= cnt) wa = 0.f;
            if (ib >= cnt) wb = 0.f;
            int sa = pa & 0xffff, ra = pa >> 16;
            int sb = pb & 0xffff, rb = pb >> 16;
            // issue both independent row loads before any FMA
            uint4 rawa = *(const uint4*)&xW[((size_t)ra * NN + sa) * HH + c8];
            uint4 rawb = *(const uint4*)&xW[((size_t)rb * NN + sb) * HH + c8];
            const __half2* ha = (const __half2*)&rawa;
            const __half2* hb = (const __half2*)&rawb;
#pragma unroll
            for (int k = 0; k < 4; k++) {
                float2 fa = __half22float2(ha[k]);
                acc[2*k]   += wa * fa.x;
                acc[2*k+1] += wa * fa.y;
            }
#pragma unroll
            for (int k = 0; k < 4; k++) {
                float2 fb = __half22float2(hb[k]);
                acc[2*k]   += wb * fb.x;
                acc[2*k+1] += wb * fb.y;
            }
        }
    }
#pragma unroll
    for (int j = 0; j < 8; j++)
        acc[j] += __shfl_xor_sync(0xffffffffu, acc[j], 16);
#pragma unroll
    for (int off = 16; off; off >>= 1)
        den += __shfl_xor_sync(0xffffffffu, den, off);

    if (lane < 16) {
        float inv = 1.f / (den + 1e-16f);
        float4 b0 = *(const float4*)&bias[lane * 8];
        float4 b1 = *(const float4*)&bias[lane * 8 + 4];
        float o[8];
        o[0] = fmaxf(acc[0] * inv + b0.x, 0.f);
        o[1] = fmaxf(acc[1] * inv + b0.y, 0.f);
        o[2] = fmaxf(acc[2] * inv + b0.z, 0.f);
        o[3] = fmaxf(acc[3] * inv + b0.w, 0.f);
        o[4] = fmaxf(acc[4] * inv + b1.x, 0.f);
        o[5] = fmaxf(acc[5] * inv + b1.y, 0.f);
        o[6] = fmaxf(acc[6] * inv + b1.z, 0.f);
        o[7] = fmaxf(acc[7] * inv + b1.w, 0.f);
        uint32_t hw[4];
        __half2 h;
        h = __floats2half2_rn(o[0], o[1]); hw[0] = *(uint32_t*)&h;
        h = __floats2half2_rn(o[2], o[3]); hw[1] = *(uint32_t*)&h;
        h = __floats2half2_rn(o[4], o[5]); hw[2] = *(uint32_t*)&h;
        h = __floats2half2_rn(o[6], o[7]); hw[3] = *(uint32_t*)&h;
        *(uint4*)&outH[(size_t)n * HH + lane * 8] = make_uint4(hw[0], hw[1], hw[2], hw[3]);
    }
}

// ---------------- launch ------------------------------------------------------
extern "C" void kernel_launch(void* const* d_in, const int* in_sizes, int n_in,
                              void* d_out, int out_size)
{
    const float* x  = (const float*)d_in[0];
    const int*   ei = (const int*)  d_in[1];
    const int*   et = (const int*)  d_in[2];
    const float* W1 = (const float*)d_in[4];
    const float* q1 = (const float*)d_in[5];
    const float* k1 = (const float*)d_in[6];
    const float* b1 = (const float*)d_in[7];
    const float* W2 = (const float*)d_in[8];
    const float* q2 = (const float*)d_in[9];
    const float* k2 = (const float*)d_in[10];
    const float* b2 = (const float*)d_in[11];
    const float* Wl = (const float*)d_in[12];
    const float* bl = (const float*)d_in[13];
    float* out = (float*)d_out;

    const int* srcp = ei;
    const int* tgtp = ei + EE;

    float *psq, *psk;
    __half *pxW, *pXf, *pHf;
    __half *pB1h, *pB1l, *pB2h, *pB2l, *pBlh, *pBll;
    cudaGetSymbolAddress((void**)&pxW, g_xW16);
    cudaGetSymbolAddress((void**)&psq, g_sq);
    cudaGetSymbolAddress((void**)&psk, g_sk);
    cudaGetSymbolAddress((void**)&pXf, g_Xf);
    cudaGetSymbolAddress((void**)&pHf, g_Hf);
    cudaGetSymbolAddress((void**)&pB1h, g_B1hi);
    cudaGetSymbolAddress((void**)&pB1l, g_B1lo);
    cudaGetSymbolAddress((void**)&pB2h, g_B2hi);
    cudaGetSymbolAddress((void**)&pB2l, g_B2lo);
    cudaGetSymbolAddress((void**)&pBlh, g_Blhi);
    cudaGetSymbolAddress((void**)&pBll, g_Bllo);

    cudaFuncSetAttribute(k_gemm_tc<false>, cudaFuncAttributeMaxDynamicSharedMemorySize, SMEM_TC);
    cudaFuncSetAttribute(k_gemm_tc<true>,  cudaFuncAttributeMaxDynamicSharedMemorySize, SMEM_TC);

    const int GT128 = (NN + 127) / 128;        // 391
    dim3 tc_grid(GT128, RR);
    const int agg_blocks = (NN * 32 + 255) / 256;
    const int EB = (EE + 255) / 256;

    // Launch order keeps k_gemm_tc (layer 1) as the 4th launch -> ncu capture.
    k_convX<<<(NN * 16 + 255) / 256, 256>>>(x, pXf);   // also zeroes g_cursor
    k_prep<<<((2 * RR + 1) * 16384 + 255) / 256, 256>>>(W1, W2, Wl);
    k_hist<<<EB, 256>>>(tgtp);
    k_gemm_tc<false><<<tc_grid, 256, SMEM_TC>>>(pXf, pB1h, pB1l, pxW, nullptr,
                                                psq, psk, q1, k1, nullptr);   // 4th
    k_scan_one<<<1, SCAN_T>>>();
    k_fill<<<EB, 256>>>(srcp, tgtp, et);

    k_agg<<<agg_blocks, 256>>>(pxW, psq, psk, b1, pHf);

    k_gemm_tc<false><<<tc_grid, 256, SMEM_TC>>>(pHf, pB2h, pB2l, pxW, nullptr,
                                                psq, psk, q2, k2, nullptr);
    k_agg<<<agg_blocks, 256>>>(pxW, psq, psk, b2, pHf);

    k_gemm_tc<true><<<dim3(GT128, 1), 256, SMEM_TC>>>(pHf, pBlh, pBll, nullptr, out,
                                                      nullptr, nullptr, nullptr, nullptr, bl);
    (void)in_sizes; (void)n_in; (void)out_size;
}

// round 14
// speedup vs baseline: 1.1540x; 1.1129x over previous
#include <cuda_runtime.h>
#include <cuda_bf16.h>
#include <cuda_fp16.h>
#include <cstdint>

#define NN   50000
#define EE   800000
#define RR   8
#define HH   128
#define NEG  0.2f
#define SCAN_T 1024

// ---------------- scratch (device globals; no runtime allocation) -------------
__device__ __half g_xW16[RR * NN * HH];    // [R,N,H] per-relation transforms (fp16)
__device__ float g_sq[RR * NN];            // xW . q (fp32)
__device__ float g_sk[RR * NN];            // xW . k
__device__ int   g_rowptr[NN + 1];
__device__ int   g_cursor[NN];
__device__ int   g_edges [EE];             // packed: src | (etype<<16), CSR order
// fp16 activation images
__device__ __half g_Xf[NN * HH];
__device__ __half g_Hf[NN * HH];           // layer outputs (reused l1 -> l2)
// fp16 weight images, [R][N][K] plain layout (single term)
__device__ __half g_B1[RR * 16384];
__device__ __half g_B2[RR * 16384];
__device__ __half g_Bl[16384];             // final linear (Wl, no transpose)

// ---------------- PTX helpers -------------------------------------------------
__device__ __forceinline__ uint32_t smem_u32(const void* p) {
    uint32_t a;
    asm("{ .reg .u64 t; cvta.to.shared.u64 t, %1; cvt.u32.u64 %0, t; }" : "=r"(a) : "l"(p));
    return a;
}
__device__ __forceinline__ void ldsm4(uint32_t* r, uint32_t addr) {
    asm volatile("ldmatrix.sync.aligned.m8n8.x4.shared.b16 {%0,%1,%2,%3}, [%4];"
                 : "=r"(r[0]), "=r"(r[1]), "=r"(r[2]), "=r"(r[3]) : "r"(addr));
}
__device__ __forceinline__ void mma16816(float* c, const uint32_t* a,
                                         uint32_t b0, uint32_t b1) {
    asm volatile(
        "mma.sync.aligned.m16n8k16.row.col.f32.f16.f16.f32 "
        "{%0,%1,%2,%3}, {%4,%5,%6,%7}, {%8,%9}, {%0,%1,%2,%3};"
        : "+f"(c[0]), "+f"(c[1]), "+f"(c[2]), "+f"(c[3])
        : "r"(a[0]), "r"(a[1]), "r"(a[2]), "r"(a[3]), "r"(b0), "r"(b1));
}

// smem geometry
#define ROWB 272                      // padded fp16 row: 136 halves = 272 B
#define BTILE (128 * ROWB)            // 34816 (128 rows)
#define SMEM_TC (2 * BTILE)           // 69632: A(128 rows) + B
#define F32STRIDE 528                 // fp32 epilogue staging row stride (bytes)

// ---------------- activation conversion + degree zero -------------------------
__global__ void k_convX(const float* __restrict__ X, __half* __restrict__ Xf) {
    int c = blockIdx.x * blockDim.x + threadIdx.x;     // NN*16 chunks of 8
    if (c < NN) g_cursor[c] = 0;                       // folded zero_deg
    if (c >= NN * 16) return;
    const float4* p = (const float4*)(X + (size_t)c * 8);
    float4 f0 = p[0], f1 = p[1];
    uint32_t w[4];
    __half2 h;
    h = __floats2half2_rn(f0.x, f0.y); w[0] = *(uint32_t*)&h;
    h = __floats2half2_rn(f0.z, f0.w); w[1] = *(uint32_t*)&h;
    h = __floats2half2_rn(f1.x, f1.y); w[2] = *(uint32_t*)&h;
    h = __floats2half2_rn(f1.z, f1.w); w[3] = *(uint32_t*)&h;
    *(uint4*)(Xf + (size_t)c * 8) = make_uint4(w[0], w[1], w[2], w[3]);
}

// ---------------- weight prep: all weights -> fp16 images ---------------------
__global__ void k_prep(const float* __restrict__ W1, const float* __restrict__ W2,
                       const float* __restrict__ Wl) {
    int idx = blockIdx.x * blockDim.x + threadIdx.x;
    const int RW = RR * 16384;
    if (idx >= 2 * RW + 16384) return;
    float w;
    __half* dst;
    int dsti;
    if (idx < 2 * RW) {
        const float* W = (idx < RW) ? W1 : W2;
        int i = (idx < RW) ? idx : idx - RW;
        int r = i >> 14, rem = i & 16383;
        int n = rem >> 7, k = rem & 127;
        w = W[r * 16384 + k * 128 + n];          // transpose: Wt[n][k] = W[k][n]
        dst = (idx < RW) ? g_B1 : g_B2;
        dsti = r * 16384 + n * 128 + k;
    } else {
        int i = idx - 2 * RW;
        w = Wl[i];                               // B[j][k] = Wl[j][k], no transpose
        dst = g_Bl; dsti = i;
    }
    dst[dsti] = __float2half_rn(w);
}

// ---------------- CSR build ---------------------------------------------------
__global__ void k_hist(const int* __restrict__ tgt) {
    int e = blockIdx.x * blockDim.x + threadIdx.x;
    if (e < EE) atomicAdd(&g_cursor[tgt[e]], 1);
}
__global__ void __launch_bounds__(SCAN_T) k_scan_one() {
    __shared__ int part[SCAN_T];
    int t = threadIdx.x;
    const int per = (NN + SCAN_T - 1) / SCAN_T;
    int lo = t * per;
    int hi = lo + per; if (hi > NN) hi = NN;
    int s = 0;
    for (int i = lo; i < hi; i++) s += g_cursor[i];
    part[t] = s;
    __syncthreads();
    for (int off = 1; off < SCAN_T; off <<= 1) {
        int v = (t >= off) ? part[t - off] : 0;
        __syncthreads();
        part[t] += v;
        __syncthreads();
    }
    int run = (t > 0) ? part[t - 1] : 0;
    for (int i = lo; i < hi; i++) {
        int d = g_cursor[i];
        g_rowptr[i] = run;
        g_cursor[i] = run;
        run += d;
    }
    if (t == 0) g_rowptr[NN] = EE;
}
__global__ void k_fill(const int* __restrict__ src, const int* __restrict__ tgt,
                       const int* __restrict__ etype) {
    int e = blockIdx.x * blockDim.x + threadIdx.x;
    if (e < EE) {
        int t = tgt[e];
        int pos = atomicAdd(&g_cursor[t], 1);
        g_edges[pos] = src[e] | (etype[e] << 16);
    }
}

// ---------------- HMMA GEMM (BM=128, BN=128, warp tile 64x32, fp16xfp16) ------
// FINAL=0: Y16[r] = fp16(A @ B[r]^T), fused sq/sk scores.
// FINAL=1: Yf = A @ Wl^T + bias (fp32, straight to d_out).
template <bool FINAL>
__global__ void __launch_bounds__(256, 2)
k_gemm_tc(const __half* __restrict__ Ag, const __half* __restrict__ Bg,
          __half* __restrict__ Y16, float* __restrict__ Yf,
          float* __restrict__ sq, float* __restrict__ sk,
          const float* __restrict__ qv, const float* __restrict__ kv,
          const float* __restrict__ bias)
{
    extern __shared__ __align__(16) char dynsm[];
    char* sA = dynsm;                 // 128 rows
    char* sB = dynsm + BTILE;

    __shared__ float s_q[128], s_k[128], s_b[128];
    __shared__ float s_redq[512], s_redk[512];

    const int tid  = threadIdx.x;
    const int wid  = tid >> 5;
    const int lane = tid & 31;
    const int mw   = wid & 1;          // m offset 64*mw
    const int nw   = wid >> 1;         // n offset 32*nw
    const int r    = blockIdx.y;
    const int row0 = blockIdx.x * 128;

    if (!FINAL) {
        if (tid < 128) { s_q[tid] = qv[tid]; s_k[tid] = kv[tid]; }
    } else {
        if (tid < 128) s_b[tid] = bias[tid];
    }

    // --- B copy gmem [N=128][K=128] -> smem padded rows ---
    {
        const uint4* gb = (const uint4*)(Bg + (size_t)r * 16384);
#pragma unroll
        for (int i = 0; i < 8; i++) {
            int c = tid + 256 * i;
            int row = c >> 4, c16 = c & 15;
            *(uint4*)(sB + row * ROWB + c16 * 16) = gb[c];
        }
    }
    // --- A copy: fp16 rows -> smem padded (128 rows) ---
#pragma unroll
    for (int i = 0; i < 8; i++) {
        int c = tid + 256 * i;               // 2048 chunks of 8 halves
        int row = c >> 4, seg = c & 15;
        int grow = row0 + row;
        uint4 v = make_uint4(0, 0, 0, 0);
        if (grow < NN)
            v = *(const uint4*)(Ag + (size_t)grow * HH + seg * 8);
        *(uint4*)(sA + row * ROWB + seg * 16) = v;
    }
    __syncthreads();

    // --- mainloop: c += A*B ---
    float acc[4][4][4];
#pragma unroll
    for (int mt = 0; mt < 4; mt++)
#pragma unroll
        for (int nt = 0; nt < 4; nt++)
#pragma unroll
            for (int j = 0; j < 4; j++) acc[mt][nt][j] = 0.f;

    const uint32_t aB = smem_u32(sA);
    const uint32_t bB = smem_u32(sB);
    const int arow  = mw * 64 + (lane & 7) + ((lane >> 3) & 1) * 8;
    const int akcol = (lane >> 4) * 8;
    const uint32_t aoff = (uint32_t)(arow * ROWB + akcol * 2);
    const int brow  = nw * 32 + (lane & 7) + ((lane >> 4) & 1) * 8;
    const int bkcol = ((lane >> 3) & 1) * 8;
    const uint32_t boff = (uint32_t)(brow * ROWB + bkcol * 2);

#pragma unroll
    for (int ks = 0; ks < 8; ks++) {
        const uint32_t ko = ks * 32;
        uint32_t a[4][4], b[2][4];
#pragma unroll
        for (int mt = 0; mt < 4; mt++)
            ldsm4(a[mt], aB + aoff + mt * 16 * ROWB + ko);
        ldsm4(b[0], bB + boff + ko);
        ldsm4(b[1], bB + boff + 16 * ROWB + ko);
#pragma unroll
        for (int mt = 0; mt < 4; mt++)
#pragma unroll
            for (int p = 0; p < 2; p++) {
                mma16816(acc[mt][2*p],   a[mt], b[p][0], b[p][1]);
                mma16816(acc[mt][2*p+1], a[mt], b[p][2], b[p][3]);
            }
    }
    __syncthreads();    // done reading sA/sB; reuse smem as staging

    if (!FINAL) {
        float pq[8], pk[8];
#pragma unroll
        for (int j = 0; j < 8; j++) { pq[j] = 0.f; pk[j] = 0.f; }
#pragma unroll
        for (int mt = 0; mt < 4; mt++) {
            const int lrow = mw * 64 + mt * 16 + (lane >> 2);
#pragma unroll
            for (int nt = 0; nt < 4; nt++) {
                const int col = nw * 32 + nt * 8 + (lane & 3) * 2;
                float c0 = acc[mt][nt][0], c1 = acc[mt][nt][1];
                float c2 = acc[mt][nt][2], c3 = acc[mt][nt][3];
                float q0 = s_q[col], q1 = s_q[col + 1];
                float k0 = s_k[col], k1 = s_k[col + 1];
                pq[mt*2]   += c0 * q0 + c1 * q1;
                pq[mt*2+1] += c2 * q0 + c3 * q1;
                pk[mt*2]   += c0 * k0 + c1 * k1;
                pk[mt*2+1] += c2 * k0 + c3 * k1;
                *(__half2*)(sA + lrow * ROWB + col * 2)       = __floats2half2_rn(c0, c1);
                *(__half2*)(sA + (lrow + 8) * ROWB + col * 2) = __floats2half2_rn(c2, c3);
            }
        }
#pragma unroll
        for (int off = 1; off <= 2; off <<= 1)
#pragma unroll
            for (int j = 0; j < 8; j++) {
                pq[j] += __shfl_xor_sync(0xffffffffu, pq[j], off);
                pk[j] += __shfl_xor_sync(0xffffffffu, pk[j], off);
            }
        if ((lane & 3) == 0) {
#pragma unroll
            for (int mt = 0; mt < 4; mt++) {
                int lrow = mw * 64 + mt * 16 + (lane >> 2);
                s_redq[nw * 128 + lrow]     = pq[mt*2];
                s_redq[nw * 128 + lrow + 8] = pq[mt*2+1];
                s_redk[nw * 128 + lrow]     = pk[mt*2];
                s_redk[nw * 128 + lrow + 8] = pk[mt*2+1];
            }
        }
        __syncthreads();
        if (tid < 128) {
            int grow = row0 + tid;
            if (grow < NN) {
                sq[r * NN + grow] = s_redq[tid] + s_redq[128 + tid] + s_redq[256 + tid] + s_redq[384 + tid];
                sk[r * NN + grow] = s_redk[tid] + s_redk[128 + tid] + s_redk[256 + tid] + s_redk[384 + tid];
            }
        }
        // --- coalesced bulk copy: 128 rows x 128 halves ---
#pragma unroll
        for (int i = 0; i < 8; i++) {
            int c = tid + 256 * i;
            int row = c >> 4, seg = c & 15;
            int grow = row0 + row;
            if (grow < NN)
                *(uint4*)&Y16[((size_t)r * NN + grow) * HH + seg * 8] =
                    *(const uint4*)(sA + row * ROWB + seg * 16);
        }
    } else {
        // --- fp32 staging with bias (128 rows x 528B = 67.6KB <= 69.6KB), copy ---
#pragma unroll
        for (int mt = 0; mt < 4; mt++) {
            const int lrow = mw * 64 + mt * 16 + (lane >> 2);
#pragma unroll
            for (int nt = 0; nt < 4; nt++) {
                const int col = nw * 32 + nt * 8 + (lane & 3) * 2;
                float b0 = s_b[col], b1 = s_b[col + 1];
                *(float2*)(sA + lrow * F32STRIDE + col * 4) =
                    make_float2(acc[mt][nt][0] + b0, acc[mt][nt][1] + b1);
                *(float2*)(sA + (lrow + 8) * F32STRIDE + col * 4) =
                    make_float2(acc[mt][nt][2] + b0, acc[mt][nt][3] + b1);
            }
        }
        __syncthreads();
#pragma unroll
        for (int i = 0; i < 16; i++) {
            int c = tid + 256 * i;               // 4096 uint4
            int row = c >> 5, seg = c & 31;
            int grow = row0 + row;
            if (grow < NN)
                *(uint4*)&Yf[(size_t)grow * HH + seg * 4] =
                    *(const uint4*)(sA + row * F32STRIDE + seg * 16);
        }
    }
}

// ---------------- single-pass softmax + aggregation (warp per node) -----------
// Scores computed in-warp per 32-edge batch (hidden under gather latency).
// Gather: 4 edges in flight (2 pairs x half-warps), loads issued before FMAs.
__global__ void __launch_bounds__(256)
k_agg(const __half* __restrict__ xW, const float* __restrict__ sq,
      const float* __restrict__ sk, const float* __restrict__ bias,
      __half* __restrict__ outH)
{
    int warp = (blockIdx.x * blockDim.x + threadIdx.x) >> 5;
    int lane = threadIdx.x & 31;
    if (warp >= NN) return;
    const int n     = warp;
    const int start = g_rowptr[n];
    const int end   = g_rowptr[n + 1];

    float sqv = (lane < RR) ? sq[lane * NN + n] : 0.f;

    const int half16 = lane >> 4;           // which edge of each pair
    const int c8     = (lane & 15) * 8;     // 8-half column group

    float acc[8] = {0.f, 0.f, 0.f, 0.f, 0.f, 0.f, 0.f, 0.f};
    float den = 0.f;
    for (int j0 = start; j0 < end; j0 += 32) {
        int j = j0 + lane;
        int p = (j < end) ? g_edges[j] : 0;
        int s = p & 0xffff, et = p >> 16;
        float v = __shfl_sync(0xffffffffu, sqv, et) + sk[et * NN + s];
        v = v > 0.f ? v : NEG * v;
        float w = (j < end) ? __expf(v) : 0.f;     // shift-invariant softmax
        den += w;
        int cnt = min(32, end - j0);
        for (int t = 0; t < cnt; t += 4) {
            int ia = t + half16;
            int ib = t + 2 + half16;
            int iac = (ia < cnt) ? ia : cnt - 1;
            int ibc = (ib < cnt) ? ib : cnt - 1;
            float wa = __shfl_sync(0xffffffffu, w, iac);
            int   pa = __shfl_sync(0xffffffffu, p, iac);
            float wb = __shfl_sync(0xffffffffu, w, ibc);
            int   pb = __shfl_sync(0xffffffffu, p, ibc);
            if (ia >= cnt) wa = 0.f;
            if (ib >= cnt) wb = 0.f;
            int sa = pa & 0xffff, ra = pa >> 16;
            int sb = pb & 0xffff, rb = pb >> 16;
            uint4 rawa = *(const uint4*)&xW[((size_t)ra * NN + sa) * HH + c8];
            uint4 rawb = *(const uint4*)&xW[((size_t)rb * NN + sb) * HH + c8];
            const __half2* ha = (const __half2*)&rawa;
            const __half2* hb = (const __half2*)&rawb;
#pragma unroll
            for (int k = 0; k < 4; k++) {
                float2 fa = __half22float2(ha[k]);
                acc[2*k]   += wa * fa.x;
                acc[2*k+1] += wa * fa.y;
            }
#pragma unroll
            for (int k = 0; k < 4; k++) {
                float2 fb = __half22float2(hb[k]);
                acc[2*k]   += wb * fb.x;
                acc[2*k+1] += wb * fb.y;
            }
        }
    }
#pragma unroll
    for (int j = 0; j < 8; j++)
        acc[j] += __shfl_xor_sync(0xffffffffu, acc[j], 16);
#pragma unroll
    for (int off = 16; off; off >>= 1)
        den += __shfl_xor_sync(0xffffffffu, den, off);

    if (lane < 16) {
        float inv = 1.f / (den + 1e-16f);
        float4 b0 = *(const float4*)&bias[lane * 8];
        float4 b1 = *(const float4*)&bias[lane * 8 + 4];
        float o[8];
        o[0] = fmaxf(acc[0] * inv + b0.x, 0.f);
        o[1] = fmaxf(acc[1] * inv + b0.y, 0.f);
        o[2] = fmaxf(acc[2] * inv + b0.z, 0.f);
        o[3] = fmaxf(acc[3] * inv + b0.w, 0.f);
        o[4] = fmaxf(acc[4] * inv + b1.x, 0.f);
        o[5] = fmaxf(acc[5] * inv + b1.y, 0.f);
        o[6] = fmaxf(acc[6] * inv + b1.z, 0.f);
        o[7] = fmaxf(acc[7] * inv + b1.w, 0.f);
        uint32_t hw[4];
        __half2 h;
        h = __floats2half2_rn(o[0], o[1]); hw[0] = *(uint32_t*)&h;
        h = __floats2half2_rn(o[2], o[3]); hw[1] = *(uint32_t*)&h;
        h = __floats2half2_rn(o[4], o[5]); hw[2] = *(uint32_t*)&h;
        h = __floats2half2_rn(o[6], o[7]); hw[3] = *(uint32_t*)&h;
        *(uint4*)&outH[(size_t)n * HH + lane * 8] = make_uint4(hw[0], hw[1], hw[2], hw[3]);
    }
}

// ---------------- launch ------------------------------------------------------
extern "C" void kernel_launch(void* const* d_in, const int* in_sizes, int n_in,
                              void* d_out, int out_size)
{
    const float* x  = (const float*)d_in[0];
    const int*   ei = (const int*)  d_in[1];
    const int*   et = (const int*)  d_in[2];
    const float* W1 = (const float*)d_in[4];
    const float* q1 = (const float*)d_in[5];
    const float* k1 = (const float*)d_in[6];
    const float* b1 = (const float*)d_in[7];
    const float* W2 = (const float*)d_in[8];
    const float* q2 = (const float*)d_in[9];
    const float* k2 = (const float*)d_in[10];
    const float* b2 = (const float*)d_in[11];
    const float* Wl = (const float*)d_in[12];
    const float* bl = (const float*)d_in[13];
    float* out = (float*)d_out;

    const int* srcp = ei;
    const int* tgtp = ei + EE;

    float *psq, *psk;
    __half *pxW, *pXf, *pHf;
    __half *pB1, *pB2, *pBl;
    cudaGetSymbolAddress((void**)&pxW, g_xW16);
    cudaGetSymbolAddress((void**)&psq, g_sq);
    cudaGetSymbolAddress((void**)&psk, g_sk);
    cudaGetSymbolAddress((void**)&pXf, g_Xf);
    cudaGetSymbolAddress((void**)&pHf, g_Hf);
    cudaGetSymbolAddress((void**)&pB1, g_B1);
    cudaGetSymbolAddress((void**)&pB2, g_B2);
    cudaGetSymbolAddress((void**)&pBl, g_Bl);

    cudaFuncSetAttribute(k_gemm_tc<false>, cudaFuncAttributeMaxDynamicSharedMemorySize, SMEM_TC);
    cudaFuncSetAttribute(k_gemm_tc<true>,  cudaFuncAttributeMaxDynamicSharedMemorySize, SMEM_TC);

    const int GT128 = (NN + 127) / 128;        // 391
    dim3 tc_grid(GT128, RR);
    const int agg_blocks = (NN * 32 + 255) / 256;
    const int EB = (EE + 255) / 256;

    // Launch order keeps k_gemm_tc (layer 1) as the 4th launch -> ncu capture.
    k_convX<<<(NN * 16 + 255) / 256, 256>>>(x, pXf);   // also zeroes g_cursor
    k_prep<<<((2 * RR + 1) * 16384 + 255) / 256, 256>>>(W1, W2, Wl);
    k_hist<<<EB, 256>>>(tgtp);
    k_gemm_tc<false><<<tc_grid, 256, SMEM_TC>>>(pXf, pB1, pxW, nullptr,
                                                psq, psk, q1, k1, nullptr);   // 4th
    k_scan_one<<<1, SCAN_T>>>();
    k_fill<<<EB, 256>>>(srcp, tgtp, et);

    k_agg<<<agg_blocks, 256>>>(pxW, psq, psk, b1, pHf);

    k_gemm_tc<false><<<tc_grid, 256, SMEM_TC>>>(pHf, pB2, pxW, nullptr,
                                                psq, psk, q2, k2, nullptr);
    k_agg<<<agg_blocks, 256>>>(pxW, psq, psk, b2, pHf);

    k_gemm_tc<true><<<dim3(GT128, 1), 256, SMEM_TC>>>(pHf, pBl, nullptr, out,
                                                      nullptr, nullptr, nullptr, nullptr, bl);
    (void)in_sizes; (void)n_in; (void)out_size;
}

// round 15
// speedup vs baseline: 1.1748x; 1.0181x over previous
#include <cuda_runtime.h>
#include <cuda_bf16.h>
#include <cuda_fp16.h>
#include <cstdint>

#define NN   50000
#define EE   800000
#define RR   8
#define HH   128
#define NEG  0.2f
#define SCAN_T 1024

// ---------------- scratch (device globals; no runtime allocation) -------------
__device__ __half g_xW16[RR * NN * HH];    // [R,N,H] per-relation transforms (fp16)
__device__ float g_sq[RR * NN];            // xW . q (fp32)
__device__ float g_sk[RR * NN];            // xW . k
__device__ int   g_rowptr[NN + 1];
__device__ int   g_cursor[NN];
__device__ int   g_edges [EE];             // packed: src | (etype<<16), CSR order
// fp16 activation images
__device__ __half g_Xf[NN * HH];
__device__ __half g_Hf[NN * HH];           // layer outputs (reused l1 -> l2)
// fp16 weight images, [R][N][K] plain layout
__device__ __half g_B1[RR * 16384];
__device__ __half g_B2[RR * 16384];
__device__ __half g_Bl[16384];             // final linear (Wl, no transpose)

// ---------------- PTX helpers -------------------------------------------------
__device__ __forceinline__ uint32_t smem_u32(const void* p) {
    uint32_t a;
    asm("{ .reg .u64 t; cvta.to.shared.u64 t, %1; cvt.u32.u64 %0, t; }" : "=r"(a) : "l"(p));
    return a;
}
__device__ __forceinline__ void ldsm4(uint32_t* r, uint32_t addr) {
    asm volatile("ldmatrix.sync.aligned.m8n8.x4.shared.b16 {%0,%1,%2,%3}, [%4];"
                 : "=r"(r[0]), "=r"(r[1]), "=r"(r[2]), "=r"(r[3]) : "r"(addr));
}
__device__ __forceinline__ void mma16816(float* c, const uint32_t* a,
                                         uint32_t b0, uint32_t b1) {
    asm volatile(
        "mma.sync.aligned.m16n8k16.row.col.f32.f16.f16.f32 "
        "{%0,%1,%2,%3}, {%4,%5,%6,%7}, {%8,%9}, {%0,%1,%2,%3};"
        : "+f"(c[0]), "+f"(c[1]), "+f"(c[2]), "+f"(c[3])
        : "r"(a[0]), "r"(a[1]), "r"(a[2]), "r"(a[3]), "r"(b0), "r"(b1));
}

// smem geometry
#define ROWB 272                      // padded fp16 row: 136 halves = 272 B
#define BTILE (128 * ROWB)            // 34816 (128 rows)
#define SMEM_TC (2 * BTILE)           // 69632: A(128 rows) + B
#define F32STRIDE 528                 // fp32 epilogue staging row stride (bytes)

// ---------------- weight prep (+ cursor zero) ---------------------------------
__global__ void k_prep(const float* __restrict__ W1, const float* __restrict__ W2,
                       const float* __restrict__ Wl) {
    int idx = blockIdx.x * blockDim.x + threadIdx.x;
    if (idx < NN) g_cursor[idx] = 0;         // zero degree counters (before hist)
    const int RW = RR * 16384;
    if (idx >= 2 * RW + 16384) return;
    float w;
    __half* dst;
    int dsti;
    if (idx < 2 * RW) {
        const float* W = (idx < RW) ? W1 : W2;
        int i = (idx < RW) ? idx : idx - RW;
        int r = i >> 14, rem = i & 16383;
        int n = rem >> 7, k = rem & 127;
        w = W[r * 16384 + k * 128 + n];      // transpose: Wt[n][k] = W[k][n]
        dst = (idx < RW) ? g_B1 : g_B2;
        dsti = r * 16384 + n * 128 + k;
    } else {
        int i = idx - 2 * RW;
        w = Wl[i];                           // B[j][k] = Wl[j][k], no transpose
        dst = g_Bl; dsti = i;
    }
    dst[dsti] = __float2half_rn(w);
}

// ---------------- activation conversion + degree histogram --------------------
// NN*16 == EE, so the same grid covers both jobs.
__global__ void k_convX(const float* __restrict__ X, __half* __restrict__ Xf,
                        const int* __restrict__ tgt) {
    int c = blockIdx.x * blockDim.x + threadIdx.x;
    if (c < EE) atomicAdd(&g_cursor[tgt[c]], 1);       // folded histogram
    if (c >= NN * 16) return;
    const float4* p = (const float4*)(X + (size_t)c * 8);
    float4 f0 = p[0], f1 = p[1];
    uint32_t w[4];
    __half2 h;
    h = __floats2half2_rn(f0.x, f0.y); w[0] = *(uint32_t*)&h;
    h = __floats2half2_rn(f0.z, f0.w); w[1] = *(uint32_t*)&h;
    h = __floats2half2_rn(f1.x, f1.y); w[2] = *(uint32_t*)&h;
    h = __floats2half2_rn(f1.z, f1.w); w[3] = *(uint32_t*)&h;
    *(uint4*)(Xf + (size_t)c * 8) = make_uint4(w[0], w[1], w[2], w[3]);
}

// ---------------- CSR scan + fill ---------------------------------------------
__global__ void __launch_bounds__(SCAN_T) k_scan_one() {
    __shared__ int part[SCAN_T];
    int t = threadIdx.x;
    const int per = (NN + SCAN_T - 1) / SCAN_T;
    int lo = t * per;
    int hi = lo + per; if (hi > NN) hi = NN;
    int s = 0;
    for (int i = lo; i < hi; i++) s += g_cursor[i];
    part[t] = s;
    __syncthreads();
    for (int off = 1; off < SCAN_T; off <<= 1) {
        int v = (t >= off) ? part[t - off] : 0;
        __syncthreads();
        part[t] += v;
        __syncthreads();
    }
    int run = (t > 0) ? part[t - 1] : 0;
    for (int i = lo; i < hi; i++) {
        int d = g_cursor[i];
        g_rowptr[i] = run;
        g_cursor[i] = run;
        run += d;
    }
    if (t == 0) g_rowptr[NN] = EE;
}
__global__ void k_fill(const int* __restrict__ src, const int* __restrict__ tgt,
                       const int* __restrict__ etype) {
    int e = blockIdx.x * blockDim.x + threadIdx.x;
    if (e < EE) {
        int t = tgt[e];
        int pos = atomicAdd(&g_cursor[t], 1);
        g_edges[pos] = src[e] | (etype[e] << 16);
    }
}

// ---------------- HMMA GEMM (BM=128, BN=128, warp 64x32, fp16xfp16) -----------
// Non-final: each block handles TWO relations (A tile resident across both);
// Y16[r] = fp16(A @ B[r]^T) with fused sq/sk scores; staging in sB.
// FINAL: one relation (Wl); Yf = A @ Wl^T + bias (fp32); staging in sA region.
template <bool FINAL>
__global__ void __launch_bounds__(256, 2)
k_gemm_tc(const __half* __restrict__ Ag, const __half* __restrict__ Bg,
          __half* __restrict__ Y16, float* __restrict__ Yf,
          float* __restrict__ sq, float* __restrict__ sk,
          const float* __restrict__ qv, const float* __restrict__ kv,
          const float* __restrict__ bias)
{
    extern __shared__ __align__(16) char dynsm[];
    char* sA = dynsm;                 // 128 rows (persistent across relations)
    char* sB = dynsm + BTILE;         // B tile / fp16 staging

    __shared__ float s_q[128], s_k[128], s_b[128];
    __shared__ float s_redq[512], s_redk[512];

    const int tid  = threadIdx.x;
    const int wid  = tid >> 5;
    const int lane = tid & 31;
    const int mw   = wid & 1;          // m offset 64*mw
    const int nw   = wid >> 1;         // n offset 32*nw
    const int row0 = blockIdx.x * 128;

    if (!FINAL) {
        if (tid < 128) { s_q[tid] = qv[tid]; s_k[tid] = kv[tid]; }
    } else {
        if (tid < 128) s_b[tid] = bias[tid];
    }

    // --- A copy: fp16 rows -> smem padded (128 rows), done ONCE ---
#pragma unroll
    for (int i = 0; i < 8; i++) {
        int c = tid + 256 * i;               // 2048 chunks of 8 halves
        int row = c >> 4, seg = c & 15;
        int grow = row0 + row;
        uint4 v = make_uint4(0, 0, 0, 0);
        if (grow < NN)
            v = *(const uint4*)(Ag + (size_t)grow * HH + seg * 8);
        *(uint4*)(sA + row * ROWB + seg * 16) = v;
    }

    const uint32_t aB = smem_u32(sA);
    const uint32_t bB = smem_u32(sB);
    const int arow  = mw * 64 + (lane & 7) + ((lane >> 3) & 1) * 8;
    const int akcol = (lane >> 4) * 8;
    const uint32_t aoff = (uint32_t)(arow * ROWB + akcol * 2);
    const int brow  = nw * 32 + (lane & 7) + ((lane >> 4) & 1) * 8;
    const int bkcol = ((lane >> 3) & 1) * 8;
    const uint32_t boff = (uint32_t)(brow * ROWB + bkcol * 2);

    const int NRELS = FINAL ? 1 : 2;
    for (int rr = 0; rr < NRELS; rr++) {
        const int r = FINAL ? 0 : (blockIdx.y * 2 + rr);

        // --- B copy gmem [N=128][K=128] -> smem padded rows ---
        {
            const uint4* gb = (const uint4*)(Bg + (size_t)r * 16384);
#pragma unroll
            for (int i = 0; i < 8; i++) {
                int c = tid + 256 * i;
                int row = c >> 4, c16 = c & 15;
                *(uint4*)(sB + row * ROWB + c16 * 16) = gb[c];
            }
        }
        __syncthreads();

        // --- mainloop: c += A*B ---
        float acc[4][4][4];
#pragma unroll
        for (int mt = 0; mt < 4; mt++)
#pragma unroll
            for (int nt = 0; nt < 4; nt++)
#pragma unroll
                for (int j = 0; j < 4; j++) acc[mt][nt][j] = 0.f;

#pragma unroll
        for (int ks = 0; ks < 8; ks++) {
            const uint32_t ko = ks * 32;
            uint32_t a[4][4], b[2][4];
#pragma unroll
            for (int mt = 0; mt < 4; mt++)
                ldsm4(a[mt], aB + aoff + mt * 16 * ROWB + ko);
            ldsm4(b[0], bB + boff + ko);
            ldsm4(b[1], bB + boff + 16 * ROWB + ko);
#pragma unroll
            for (int mt = 0; mt < 4; mt++)
#pragma unroll
                for (int p = 0; p < 2; p++) {
                    mma16816(acc[mt][2*p],   a[mt], b[p][0], b[p][1]);
                    mma16816(acc[mt][2*p+1], a[mt], b[p][2], b[p][3]);
                }
        }
        __syncthreads();    // all warps done reading sB -> reuse as staging

        if (!FINAL) {
            float pq[8], pk[8];
#pragma unroll
            for (int j = 0; j < 8; j++) { pq[j] = 0.f; pk[j] = 0.f; }
#pragma unroll
            for (int mt = 0; mt < 4; mt++) {
                const int lrow = mw * 64 + mt * 16 + (lane >> 2);
#pragma unroll
                for (int nt = 0; nt < 4; nt++) {
                    const int col = nw * 32 + nt * 8 + (lane & 3) * 2;
                    float c0 = acc[mt][nt][0], c1 = acc[mt][nt][1];
                    float c2 = acc[mt][nt][2], c3 = acc[mt][nt][3];
                    float q0 = s_q[col], q1 = s_q[col + 1];
                    float k0 = s_k[col], k1 = s_k[col + 1];
                    pq[mt*2]   += c0 * q0 + c1 * q1;
                    pq[mt*2+1] += c2 * q0 + c3 * q1;
                    pk[mt*2]   += c0 * k0 + c1 * k1;
                    pk[mt*2+1] += c2 * k0 + c3 * k1;
                    *(__half2*)(sB + lrow * ROWB + col * 2)       = __floats2half2_rn(c0, c1);
                    *(__half2*)(sB + (lrow + 8) * ROWB + col * 2) = __floats2half2_rn(c2, c3);
                }
            }
#pragma unroll
            for (int off = 1; off <= 2; off <<= 1)
#pragma unroll
                for (int j = 0; j < 8; j++) {
                    pq[j] += __shfl_xor_sync(0xffffffffu, pq[j], off);
                    pk[j] += __shfl_xor_sync(0xffffffffu, pk[j], off);
                }
            if ((lane & 3) == 0) {
#pragma unroll
                for (int mt = 0; mt < 4; mt++) {
                    int lrow = mw * 64 + mt * 16 + (lane >> 2);
                    s_redq[nw * 128 + lrow]     = pq[mt*2];
                    s_redq[nw * 128 + lrow + 8] = pq[mt*2+1];
                    s_redk[nw * 128 + lrow]     = pk[mt*2];
                    s_redk[nw * 128 + lrow + 8] = pk[mt*2+1];
                }
            }
            __syncthreads();
            if (tid < 128) {
                int grow = row0 + tid;
                if (grow < NN) {
                    sq[r * NN + grow] = s_redq[tid] + s_redq[128 + tid] + s_redq[256 + tid] + s_redq[384 + tid];
                    sk[r * NN + grow] = s_redk[tid] + s_redk[128 + tid] + s_redk[256 + tid] + s_redk[384 + tid];
                }
            }
            // --- coalesced bulk copy: 128 rows x 128 halves ---
#pragma unroll
            for (int i = 0; i < 8; i++) {
                int c = tid + 256 * i;
                int row = c >> 4, seg = c & 15;
                int grow = row0 + row;
                if (grow < NN)
                    *(uint4*)&Y16[((size_t)r * NN + grow) * HH + seg * 8] =
                        *(const uint4*)(sB + row * ROWB + seg * 16);
            }
            __syncthreads();    // staging consumed before next relation's B copy
        } else {
            // --- fp32 staging with bias from sA base (A no longer needed) ---
#pragma unroll
            for (int mt = 0; mt < 4; mt++) {
                const int lrow = mw * 64 + mt * 16 + (lane >> 2);
#pragma unroll
                for (int nt = 0; nt < 4; nt++) {
                    const int col = nw * 32 + nt * 8 + (lane & 3) * 2;
                    float b0 = s_b[col], b1 = s_b[col + 1];
                    *(float2*)(sA + lrow * F32STRIDE + col * 4) =
                        make_float2(acc[mt][nt][0] + b0, acc[mt][nt][1] + b1);
                    *(float2*)(sA + (lrow + 8) * F32STRIDE + col * 4) =
                        make_float2(acc[mt][nt][2] + b0, acc[mt][nt][3] + b1);
                }
            }
            __syncthreads();
#pragma unroll
            for (int i = 0; i < 16; i++) {
                int c = tid + 256 * i;               // 4096 uint4
                int row = c >> 5, seg = c & 31;
                int grow = row0 + row;
                if (grow < NN)
                    *(uint4*)&Yf[(size_t)grow * HH + seg * 4] =
                        *(const uint4*)(sA + row * F32STRIDE + seg * 16);
            }
        }
    }
}

// ---------------- single-pass softmax + aggregation (warp per node) -----------
__global__ void __launch_bounds__(256)
k_agg(const __half* __restrict__ xW, const float* __restrict__ sq,
      const float* __restrict__ sk, const float* __restrict__ bias,
      __half* __restrict__ outH)
{
    int warp = (blockIdx.x * blockDim.x + threadIdx.x) >> 5;
    int lane = threadIdx.x & 31;
    if (warp >= NN) return;
    const int n     = warp;
    const int start = g_rowptr[n];
    const int end   = g_rowptr[n + 1];

    float sqv = (lane < RR) ? sq[lane * NN + n] : 0.f;

    const int half16 = lane >> 4;           // which edge of each pair
    const int c8     = (lane & 15) * 8;     // 8-half column group

    float acc[8] = {0.f, 0.f, 0.f, 0.f, 0.f, 0.f, 0.f, 0.f};
    float den = 0.f;
    for (int j0 = start; j0 < end; j0 += 32) {
        int j = j0 + lane;
        int p = (j < end) ? g_edges[j] : 0;
        int s = p & 0xffff, et = p >> 16;
        float v = __shfl_sync(0xffffffffu, sqv, et) + sk[et * NN + s];
        v = v > 0.f ? v : NEG * v;
        float w = (j < end) ? __expf(v) : 0.f;     // shift-invariant softmax
        den += w;
        int cnt = min(32, end - j0);
        for (int t = 0; t < cnt; t += 4) {
            int ia = t + half16;
            int ib = t + 2 + half16;
            int iac = (ia < cnt) ? ia : cnt - 1;
            int ibc = (ib < cnt) ? ib : cnt - 1;
            float wa = __shfl_sync(0xffffffffu, w, iac);
            int   pa = __shfl_sync(0xffffffffu, p, iac);
            float wb = __shfl_sync(0xffffffffu, w, ibc);
            int   pb = __shfl_sync(0xffffffffu, p, ibc);
            if (ia >= cnt) wa = 0.f;
            if (ib >= cnt) wb = 0.f;
            int sa = pa & 0xffff, ra = pa >> 16;
            int sb = pb & 0xffff, rb = pb >> 16;
            uint4 rawa = *(const uint4*)&xW[((size_t)ra * NN + sa) * HH + c8];
            uint4 rawb = *(const uint4*)&xW[((size_t)rb * NN + sb) * HH + c8];
            const __half2* ha = (const __half2*)&rawa;
            const __half2* hb = (const __half2*)&rawb;
#pragma unroll
            for (int k = 0; k < 4; k++) {
                float2 fa = __half22float2(ha[k]);
                acc[2*k]   += wa * fa.x;
                acc[2*k+1] += wa * fa.y;
            }
#pragma unroll
            for (int k = 0; k < 4; k++) {
                float2 fb = __half22float2(hb[k]);
                acc[2*k]   += wb * fb.x;
                acc[2*k+1] += wb * fb.y;
            }
        }
    }
#pragma unroll
    for (int j = 0; j < 8; j++)
        acc[j] += __shfl_xor_sync(0xffffffffu, acc[j], 16);
#pragma unroll
    for (int off = 16; off; off >>= 1)
        den += __shfl_xor_sync(0xffffffffu, den, off);

    if (lane < 16) {
        float inv = 1.f / (den + 1e-16f);
        float4 b0 = *(const float4*)&bias[lane * 8];
        float4 b1 = *(const float4*)&bias[lane * 8 + 4];
        float o[8];
        o[0] = fmaxf(acc[0] * inv + b0.x, 0.f);
        o[1] = fmaxf(acc[1] * inv + b0.y, 0.f);
        o[2] = fmaxf(acc[2] * inv + b0.z, 0.f);
        o[3] = fmaxf(acc[3] * inv + b0.w, 0.f);
        o[4] = fmaxf(acc[4] * inv + b1.x, 0.f);
        o[5] = fmaxf(acc[5] * inv + b1.y, 0.f);
        o[6] = fmaxf(acc[6] * inv + b1.z, 0.f);
        o[7] = fmaxf(acc[7] * inv + b1.w, 0.f);
        uint32_t hw[4];
        __half2 h;
        h = __floats2half2_rn(o[0], o[1]); hw[0] = *(uint32_t*)&h;
        h = __floats2half2_rn(o[2], o[3]); hw[1] = *(uint32_t*)&h;
        h = __floats2half2_rn(o[4], o[5]); hw[2] = *(uint32_t*)&h;
        h = __floats2half2_rn(o[6], o[7]); hw[3] = *(uint32_t*)&h;
        *(uint4*)&outH[(size_t)n * HH + lane * 8] = make_uint4(hw[0], hw[1], hw[2], hw[3]);
    }
}

// ---------------- launch ------------------------------------------------------
extern "C" void kernel_launch(void* const* d_in, const int* in_sizes, int n_in,
                              void* d_out, int out_size)
{
    const float* x  = (const float*)d_in[0];
    const int*   ei = (const int*)  d_in[1];
    const int*   et = (const int*)  d_in[2];
    const float* W1 = (const float*)d_in[4];
    const float* q1 = (const float*)d_in[5];
    const float* k1 = (const float*)d_in[6];
    const float* b1 = (const float*)d_in[7];
    const float* W2 = (const float*)d_in[8];
    const float* q2 = (const float*)d_in[9];
    const float* k2 = (const float*)d_in[10];
    const float* b2 = (const float*)d_in[11];
    const float* Wl = (const float*)d_in[12];
    const float* bl = (const float*)d_in[13];
    float* out = (float*)d_out;

    const int* srcp = ei;
    const int* tgtp = ei + EE;

    float *psq, *psk;
    __half *pxW, *pXf, *pHf;
    __half *pB1, *pB2, *pBl;
    cudaGetSymbolAddress((void**)&pxW, g_xW16);
    cudaGetSymbolAddress((void**)&psq, g_sq);
    cudaGetSymbolAddress((void**)&psk, g_sk);
    cudaGetSymbolAddress((void**)&pXf, g_Xf);
    cudaGetSymbolAddress((void**)&pHf, g_Hf);
    cudaGetSymbolAddress((void**)&pB1, g_B1);
    cudaGetSymbolAddress((void**)&pB2, g_B2);
    cudaGetSymbolAddress((void**)&pBl, g_Bl);

    cudaFuncSetAttribute(k_gemm_tc<false>, cudaFuncAttributeMaxDynamicSharedMemorySize, SMEM_TC);
    cudaFuncSetAttribute(k_gemm_tc<true>,  cudaFuncAttributeMaxDynamicSharedMemorySize, SMEM_TC);

    const int GT128 = (NN + 127) / 128;        // 391
    dim3 tc_grid(GT128, RR / 2);               // 2 relations per block
    const int agg_blocks = (NN * 32 + 255) / 256;
    const int EB = (EE + 255) / 256;

    // Order: prep zeroes cursor BEFORE convX's folded histogram.
    // k_gemm_tc (layer 1) stays the 4th launch -> ncu capture.
    k_prep<<<((2 * RR + 1) * 16384 + 255) / 256, 256>>>(W1, W2, Wl);   // 1 (+zero)
    k_convX<<<(NN * 16 + 255) / 256, 256>>>(x, pXf, tgtp);             // 2 (+hist)
    k_scan_one<<<1, SCAN_T>>>();                                       // 3
    k_gemm_tc<false><<<tc_grid, 256, SMEM_TC>>>(pXf, pB1, pxW, nullptr,
                                                psq, psk, q1, k1, nullptr);  // 4
    k_fill<<<EB, 256>>>(srcp, tgtp, et);                               // 5

    k_agg<<<agg_blocks, 256>>>(pxW, psq, psk, b1, pHf);                // 6

    k_gemm_tc<false><<<tc_grid, 256, SMEM_TC>>>(pHf, pB2, pxW, nullptr,
                                                psq, psk, q2, k2, nullptr);  // 7
    k_agg<<<agg_blocks, 256>>>(pxW, psq, psk, b2, pHf);                // 8

    k_gemm_tc<true><<<dim3(GT128, 1), 256, SMEM_TC>>>(pHf, pBl, nullptr, out,
                                                      nullptr, nullptr, nullptr, nullptr, bl);  // 9
    (void)in_sizes; (void)n_in; (void)out_size;
}

// round 16
// speedup vs baseline: 1.2970x; 1.1040x over previous
#include <cuda_runtime.h>
#include <cuda_bf16.h>
#include <cuda_fp16.h>
#include <cstdint>

#define NN   50000
#define EE   800000
#define RR   8
#define HH   128
#define NEG  0.2f
#define SCAN_T 1024

// ---------------- scratch (device globals; no runtime allocation) -------------
__device__ __half g_xW16[RR * NN * HH];    // [R,N,H] per-relation transforms (fp16)
__device__ float g_sq[RR * NN];            // xW . q (fp32)
__device__ float g_sk[RR * NN];            // xW . k
__device__ int   g_rowptr[NN + 1];
__device__ int   g_cursor[NN];
__device__ int   g_rank[EE];               // per-edge rank within its target node
__device__ int   g_edges [EE];             // packed: src | (etype<<16), CSR order
// fp16 activation images
__device__ __half g_Xf[NN * HH];
__device__ __half g_Hf[NN * HH];           // layer outputs (reused l1 -> l2)
// fp16 weight images, [R][N][K] plain layout
__device__ __half g_B1[RR * 16384];
__device__ __half g_B2[RR * 16384];
__device__ __half g_Bl[16384];             // final linear (Wl, no transpose)

// ---------------- PTX helpers -------------------------------------------------
__device__ __forceinline__ uint32_t smem_u32(const void* p) {
    uint32_t a;
    asm("{ .reg .u64 t; cvta.to.shared.u64 t, %1; cvt.u32.u64 %0, t; }" : "=r"(a) : "l"(p));
    return a;
}
__device__ __forceinline__ void ldsm4(uint32_t* r, uint32_t addr) {
    asm volatile("ldmatrix.sync.aligned.m8n8.x4.shared.b16 {%0,%1,%2,%3}, [%4];"
                 : "=r"(r[0]), "=r"(r[1]), "=r"(r[2]), "=r"(r[3]) : "r"(addr));
}
__device__ __forceinline__ void mma16816(float* c, const uint32_t* a,
                                         uint32_t b0, uint32_t b1) {
    asm volatile(
        "mma.sync.aligned.m16n8k16.row.col.f32.f16.f16.f32 "
        "{%0,%1,%2,%3}, {%4,%5,%6,%7}, {%8,%9}, {%0,%1,%2,%3};"
        : "+f"(c[0]), "+f"(c[1]), "+f"(c[2]), "+f"(c[3])
        : "r"(a[0]), "r"(a[1]), "r"(a[2]), "r"(a[3]), "r"(b0), "r"(b1));
}
__device__ __forceinline__ void cp_async16(uint32_t d, const void* s) {
    asm volatile("cp.async.cg.shared.global [%0], [%1], 16;" :: "r"(d), "l"(s));
}
__device__ __forceinline__ void cp_async16z(uint32_t d, const void* s, bool valid) {
    int sz = valid ? 16 : 0;
    asm volatile("cp.async.cg.shared.global [%0], [%1], 16, %2;"
                 :: "r"(d), "l"(s), "r"(sz));
}
__device__ __forceinline__ void cp_commit() {
    asm volatile("cp.async.commit_group;" ::: "memory");
}
template <int N>
__device__ __forceinline__ void cp_wait() {
    asm volatile("cp.async.wait_group %0;" :: "n"(N) : "memory");
}

// smem geometry
#define ROWB 272                      // padded fp16 row: 136 halves = 272 B
#define BTILE (128 * ROWB)            // 34816 (128 rows)
#define SMEM_TC (3 * BTILE)           // 104448: A + B double buffer
#define F32STRIDE 528                 // fp32 epilogue staging row stride (bytes)

// ---------------- weight prep (+ cursor zero) ---------------------------------
__global__ void k_prep(const float* __restrict__ W1, const float* __restrict__ W2,
                       const float* __restrict__ Wl) {
    int idx = blockIdx.x * blockDim.x + threadIdx.x;
    if (idx < NN) g_cursor[idx] = 0;         // zero degree counters (before hist)
    const int RW = RR * 16384;
    if (idx >= 2 * RW + 16384) return;
    float w;
    __half* dst;
    int dsti;
    if (idx < 2 * RW) {
        const float* W = (idx < RW) ? W1 : W2;
        int i = (idx < RW) ? idx : idx - RW;
        int r = i >> 14, rem = i & 16383;
        int n = rem >> 7, k = rem & 127;
        w = W[r * 16384 + k * 128 + n];      // transpose: Wt[n][k] = W[k][n]
        dst = (idx < RW) ? g_B1 : g_B2;
        dsti = r * 16384 + n * 128 + k;
    } else {
        int i = idx - 2 * RW;
        w = Wl[i];                           // B[j][k] = Wl[j][k], no transpose
        dst = g_Bl; dsti = i;
    }
    dst[dsti] = __float2half_rn(w);
}

// ---------------- activation conversion + histogram (records rank) ------------
// NN*16 == EE, so the same grid covers both jobs.
__global__ void k_convX(const float* __restrict__ X, __half* __restrict__ Xf,
                        const int* __restrict__ tgt) {
    int c = blockIdx.x * blockDim.x + threadIdx.x;
    if (c < EE) g_rank[c] = atomicAdd(&g_cursor[tgt[c]], 1);   // hist + rank
    if (c >= NN * 16) return;
    const float4* p = (const float4*)(X + (size_t)c * 8);
    float4 f0 = p[0], f1 = p[1];
    uint32_t w[4];
    __half2 h;
    h = __floats2half2_rn(f0.x, f0.y); w[0] = *(uint32_t*)&h;
    h = __floats2half2_rn(f0.z, f0.w); w[1] = *(uint32_t*)&h;
    h = __floats2half2_rn(f1.x, f1.y); w[2] = *(uint32_t*)&h;
    h = __floats2half2_rn(f1.z, f1.w); w[3] = *(uint32_t*)&h;
    *(uint4*)(Xf + (size_t)c * 8) = make_uint4(w[0], w[1], w[2], w[3]);
}

// ---------------- CSR scan + fill (atomic-free fill) ---------------------------
__global__ void __launch_bounds__(SCAN_T) k_scan_one() {
    __shared__ int part[SCAN_T];
    int t = threadIdx.x;
    const int per = (NN + SCAN_T - 1) / SCAN_T;
    int lo = t * per;
    int hi = lo + per; if (hi > NN) hi = NN;
    int s = 0;
    for (int i = lo; i < hi; i++) s += g_cursor[i];
    part[t] = s;
    __syncthreads();
    for (int off = 1; off < SCAN_T; off <<= 1) {
        int v = (t >= off) ? part[t - off] : 0;
        __syncthreads();
        part[t] += v;
        __syncthreads();
    }
    int run = (t > 0) ? part[t - 1] : 0;
    for (int i = lo; i < hi; i++) {
        int d = g_cursor[i];
        g_rowptr[i] = run;
        run += d;
    }
    if (t == 0) g_rowptr[NN] = EE;
}
__global__ void k_fill(const int* __restrict__ src, const int* __restrict__ tgt,
                       const int* __restrict__ etype) {
    int e = blockIdx.x * blockDim.x + threadIdx.x;
    if (e < EE) {
        int pos = g_rowptr[tgt[e]] + g_rank[e];
        g_edges[pos] = src[e] | (etype[e] << 16);
    }
}

// ---------------- HMMA GEMM (BM=128, BN=128, warp 64x32, cp.async pipe) -------
// Non-final: 2 relations per block; A resident; B double-buffered, relation 1's
// B prefetched during relation 0's mainloop. FINAL: single relation (Wl), fp32 out.
template <bool FINAL>
__global__ void __launch_bounds__(256, 2)
k_gemm_tc(const __half* __restrict__ Ag, const __half* __restrict__ Bg,
          __half* __restrict__ Y16, float* __restrict__ Yf,
          float* __restrict__ sq, float* __restrict__ sk,
          const float* __restrict__ qv, const float* __restrict__ kv,
          const float* __restrict__ bias)
{
    extern __shared__ __align__(16) char dynsm[];
    char* sA  = dynsm;                 // A tile (persistent)
    char* sB0 = dynsm + BTILE;
    char* sB1 = dynsm + 2 * BTILE;

    __shared__ float s_q[128], s_k[128], s_b[128];
    __shared__ float s_redq[512], s_redk[512];

    const int tid  = threadIdx.x;
    const int wid  = tid >> 5;
    const int lane = tid & 31;
    const int mw   = wid & 1;          // m offset 64*mw
    const int nw   = wid >> 1;         // n offset 32*nw
    const int row0 = blockIdx.x * 128;

    if (!FINAL) {
        if (tid < 128) { s_q[tid] = qv[tid]; s_k[tid] = kv[tid]; }
    } else {
        if (tid < 128) s_b[tid] = bias[tid];
    }

    const uint32_t aS  = smem_u32(sA);
    const uint32_t b0S = smem_u32(sB0);
    const uint32_t b1S = smem_u32(sB1);

    // --- prologue: async-load B(rel0) and A together ---
    {
        const int r0 = FINAL ? 0 : blockIdx.y * 2;
        const char* gb = (const char*)(Bg + (size_t)r0 * 16384);
#pragma unroll
        for (int i = 0; i < 8; i++) {
            int c = tid + 256 * i;
            int row = c >> 4, seg = c & 15;
            cp_async16(b0S + row * ROWB + seg * 16, gb + c * 16);
        }
#pragma unroll
        for (int i = 0; i < 8; i++) {
            int c = tid + 256 * i;               // 2048 chunks of 8 halves
            int row = c >> 4, seg = c & 15;
            int grow = row0 + row;
            bool ok = grow < NN;
            const char* ga = (const char*)(Ag + (size_t)(ok ? grow : 0) * HH + seg * 8);
            cp_async16z(aS + row * ROWB + seg * 16, ga, ok);
        }
        cp_commit();
        cp_wait<0>();
    }
    __syncthreads();

    const int arow  = mw * 64 + (lane & 7) + ((lane >> 3) & 1) * 8;
    const int akcol = (lane >> 4) * 8;
    const uint32_t aoff = (uint32_t)(arow * ROWB + akcol * 2) + aS;
    const int brow  = nw * 32 + (lane & 7) + ((lane >> 4) & 1) * 8;
    const int bkcol = ((lane >> 3) & 1) * 8;
    const uint32_t boffBase = (uint32_t)(brow * ROWB + bkcol * 2);

    const int NRELS = FINAL ? 1 : 2;
    for (int rr = 0; rr < NRELS; rr++) {
        const int r = FINAL ? 0 : (blockIdx.y * 2 + rr);
        char* sBc = (rr & 1) ? sB1 : sB0;
        const uint32_t boff = boffBase + ((rr & 1) ? b1S : b0S);

        // prefetch next relation's B during this mainloop
        if (!FINAL && rr == 0) {
            const char* gb = (const char*)(Bg + (size_t)(blockIdx.y * 2 + 1) * 16384);
#pragma unroll
            for (int i = 0; i < 8; i++) {
                int c = tid + 256 * i;
                int row = c >> 4, seg = c & 15;
                cp_async16(b1S + row * ROWB + seg * 16, gb + c * 16);
            }
            cp_commit();
        }

        // --- mainloop: c += A*B ---
        float acc[4][4][4];
#pragma unroll
        for (int mt = 0; mt < 4; mt++)
#pragma unroll
            for (int nt = 0; nt < 4; nt++)
#pragma unroll
                for (int j = 0; j < 4; j++) acc[mt][nt][j] = 0.f;

#pragma unroll
        for (int ks = 0; ks < 8; ks++) {
            const uint32_t ko = ks * 32;
            uint32_t a[4][4], b[2][4];
#pragma unroll
            for (int mt = 0; mt < 4; mt++)
                ldsm4(a[mt], aoff + mt * 16 * ROWB + ko);
            ldsm4(b[0], boff + ko);
            ldsm4(b[1], boff + 16 * ROWB + ko);
#pragma unroll
            for (int mt = 0; mt < 4; mt++)
#pragma unroll
                for (int p = 0; p < 2; p++) {
                    mma16816(acc[mt][2*p],   a[mt], b[p][0], b[p][1]);
                    mma16816(acc[mt][2*p+1], a[mt], b[p][2], b[p][3]);
                }
        }
        __syncthreads();    // all warps done reading sBc -> reuse as staging

        if (!FINAL) {
            float pq[8], pk[8];
#pragma unroll
            for (int j = 0; j < 8; j++) { pq[j] = 0.f; pk[j] = 0.f; }
#pragma unroll
            for (int mt = 0; mt < 4; mt++) {
                const int lrow = mw * 64 + mt * 16 + (lane >> 2);
#pragma unroll
                for (int nt = 0; nt < 4; nt++) {
                    const int col = nw * 32 + nt * 8 + (lane & 3) * 2;
                    float c0 = acc[mt][nt][0], c1 = acc[mt][nt][1];
                    float c2 = acc[mt][nt][2], c3 = acc[mt][nt][3];
                    float q0 = s_q[col], q1 = s_q[col + 1];
                    float k0 = s_k[col], k1 = s_k[col + 1];
                    pq[mt*2]   += c0 * q0 + c1 * q1;
                    pq[mt*2+1] += c2 * q0 + c3 * q1;
                    pk[mt*2]   += c0 * k0 + c1 * k1;
                    pk[mt*2+1] += c2 * k0 + c3 * k1;
                    *(__half2*)(sBc + lrow * ROWB + col * 2)       = __floats2half2_rn(c0, c1);
                    *(__half2*)(sBc + (lrow + 8) * ROWB + col * 2) = __floats2half2_rn(c2, c3);
                }
            }
#pragma unroll
            for (int off = 1; off <= 2; off <<= 1)
#pragma unroll
                for (int j = 0; j < 8; j++) {
                    pq[j] += __shfl_xor_sync(0xffffffffu, pq[j], off);
                    pk[j] += __shfl_xor_sync(0xffffffffu, pk[j], off);
                }
            if ((lane & 3) == 0) {
#pragma unroll
                for (int mt = 0; mt < 4; mt++) {
                    int lrow = mw * 64 + mt * 16 + (lane >> 2);
                    s_redq[nw * 128 + lrow]     = pq[mt*2];
                    s_redq[nw * 128 + lrow + 8] = pq[mt*2+1];
                    s_redk[nw * 128 + lrow]     = pk[mt*2];
                    s_redk[nw * 128 + lrow + 8] = pk[mt*2+1];
                }
            }
            __syncthreads();
            if (tid < 128) {
                int grow = row0 + tid;
                if (grow < NN) {
                    sq[r * NN + grow] = s_redq[tid] + s_redq[128 + tid] + s_redq[256 + tid] + s_redq[384 + tid];
                    sk[r * NN + grow] = s_redk[tid] + s_redk[128 + tid] + s_redk[256 + tid] + s_redk[384 + tid];
                }
            }
            // --- coalesced bulk copy: 128 rows x 128 halves ---
#pragma unroll
            for (int i = 0; i < 8; i++) {
                int c = tid + 256 * i;
                int row = c >> 4, seg = c & 15;
                int grow = row0 + row;
                if (grow < NN)
                    *(uint4*)&Y16[((size_t)r * NN + grow) * HH + seg * 8] =
                        *(const uint4*)(sBc + row * ROWB + seg * 16);
            }
            if (rr == 0) cp_wait<0>();   // B(rel1) must be resident
            __syncthreads();
        } else {
            // --- fp32 staging with bias spanning sA+sB0 (both dead) ---
#pragma unroll
            for (int mt = 0; mt < 4; mt++) {
                const int lrow = mw * 64 + mt * 16 + (lane >> 2);
#pragma unroll
                for (int nt = 0; nt < 4; nt++) {
                    const int col = nw * 32 + nt * 8 + (lane & 3) * 2;
                    float b0 = s_b[col], b1 = s_b[col + 1];
                    *(float2*)(sA + lrow * F32STRIDE + col * 4) =
                        make_float2(acc[mt][nt][0] + b0, acc[mt][nt][1] + b1);
                    *(float2*)(sA + (lrow + 8) * F32STRIDE + col * 4) =
                        make_float2(acc[mt][nt][2] + b0, acc[mt][nt][3] + b1);
                }
            }
            __syncthreads();
#pragma unroll
            for (int i = 0; i < 16; i++) {
                int c = tid + 256 * i;               // 4096 uint4
                int row = c >> 5, seg = c & 31;
                int grow = row0 + row;
                if (grow < NN)
                    *(uint4*)&Yf[(size_t)grow * HH + seg * 4] =
                        *(const uint4*)(sA + row * F32STRIDE + seg * 16);
            }
        }
    }
}

// ---------------- single-pass softmax + aggregation (warp per node) -----------
__global__ void __launch_bounds__(256)
k_agg(const __half* __restrict__ xW, const float* __restrict__ sq,
      const float* __restrict__ sk, const float* __restrict__ bias,
      __half* __restrict__ outH)
{
    int warp = (blockIdx.x * blockDim.x + threadIdx.x) >> 5;
    int lane = threadIdx.x & 31;
    if (warp >= NN) return;
    const int n     = warp;
    const int start = g_rowptr[n];
    const int end   = g_rowptr[n + 1];

    float sqv = (lane < RR) ? sq[lane * NN + n] : 0.f;

    const int half16 = lane >> 4;           // which edge of each pair
    const int c8     = (lane & 15) * 8;     // 8-half column group

    float acc[8] = {0.f, 0.f, 0.f, 0.f, 0.f, 0.f, 0.f, 0.f};
    float den = 0.f;
    for (int j0 = start; j0 < end; j0 += 32) {
        int j = j0 + lane;
        int p = (j < end) ? g_edges[j] : 0;
        int s = p & 0xffff, et = p >> 16;
        float v = __shfl_sync(0xffffffffu, sqv, et) + sk[et * NN + s];
        v = v > 0.f ? v : NEG * v;
        float w = (j < end) ? __expf(v) : 0.f;     // shift-invariant softmax
        den += w;
        int cnt = min(32, end - j0);
        for (int t = 0; t < cnt; t += 4) {
            int ia = t + half16;
            int ib = t + 2 + half16;
            int iac = (ia < cnt) ? ia : cnt - 1;
            int ibc = (ib < cnt) ? ib : cnt - 1;
            float wa = __shfl_sync(0xffffffffu, w, iac);
            int   pa = __shfl_sync(0xffffffffu, p, iac);
            float wb = __shfl_sync(0xffffffffu, w, ibc);
            int   pb = __shfl_sync(0xffffffffu, p, ibc);
            if (ia >= cnt) wa = 0.f;
            if (ib >= cnt) wb = 0.f;
            int sa = pa & 0xffff, ra = pa >> 16;
            int sb = pb & 0xffff, rb = pb >> 16;
            uint4 rawa = *(const uint4*)&xW[((size_t)ra * NN + sa) * HH + c8];
            uint4 rawb = *(const uint4*)&xW[((size_t)rb * NN + sb) * HH + c8];
            const __half2* ha = (const __half2*)&rawa;
            const __half2* hb = (const __half2*)&rawb;
#pragma unroll
            for (int k = 0; k < 4; k++) {
                float2 fa = __half22float2(ha[k]);
                acc[2*k]   += wa * fa.x;
                acc[2*k+1] += wa * fa.y;
            }
#pragma unroll
            for (int k = 0; k < 4; k++) {
                float2 fb = __half22float2(hb[k]);
                acc[2*k]   += wb * fb.x;
                acc[2*k+1] += wb * fb.y;
            }
        }
    }
#pragma unroll
    for (int j = 0; j < 8; j++)
        acc[j] += __shfl_xor_sync(0xffffffffu, acc[j], 16);
#pragma unroll
    for (int off = 16; off; off >>= 1)
        den += __shfl_xor_sync(0xffffffffu, den, off);

    if (lane < 16) {
        float inv = 1.f / (den + 1e-16f);
        float4 b0 = *(const float4*)&bias[lane * 8];
        float4 b1 = *(const float4*)&bias[lane * 8 + 4];
        float o[8];
        o[0] = fmaxf(acc[0] * inv + b0.x, 0.f);
        o[1] = fmaxf(acc[1] * inv + b0.y, 0.f);
        o[2] = fmaxf(acc[2] * inv + b0.z, 0.f);
        o[3] = fmaxf(acc[3] * inv + b0.w, 0.f);
        o[4] = fmaxf(acc[4] * inv + b1.x, 0.f);
        o[5] = fmaxf(acc[5] * inv + b1.y, 0.f);
        o[6] = fmaxf(acc[6] * inv + b1.z, 0.f);
        o[7] = fmaxf(acc[7] * inv + b1.w, 0.f);
        uint32_t hw[4];
        __half2 h;
        h = __floats2half2_rn(o[0], o[1]); hw[0] = *(uint32_t*)&h;
        h = __floats2half2_rn(o[2], o[3]); hw[1] = *(uint32_t*)&h;
        h = __floats2half2_rn(o[4], o[5]); hw[2] = *(uint32_t*)&h;
        h = __floats2half2_rn(o[6], o[7]); hw[3] = *(uint32_t*)&h;
        *(uint4*)&outH[(size_t)n * HH + lane * 8] = make_uint4(hw[0], hw[1], hw[2], hw[3]);
    }
}

// ---------------- launch ------------------------------------------------------
extern "C" void kernel_launch(void* const* d_in, const int* in_sizes, int n_in,
                              void* d_out, int out_size)
{
    const float* x  = (const float*)d_in[0];
    const int*   ei = (const int*)  d_in[1];
    const int*   et = (const int*)  d_in[2];
    const float* W1 = (const float*)d_in[4];
    const float* q1 = (const float*)d_in[5];
    const float* k1 = (const float*)d_in[6];
    const float* b1 = (const float*)d_in[7];
    const float* W2 = (const float*)d_in[8];
    const float* q2 = (const float*)d_in[9];
    const float* k2 = (const float*)d_in[10];
    const float* b2 = (const float*)d_in[11];
    const float* Wl = (const float*)d_in[12];
    const float* bl = (const float*)d_in[13];
    float* out = (float*)d_out;

    const int* srcp = ei;
    const int* tgtp = ei + EE;

    float *psq, *psk;
    __half *pxW, *pXf, *pHf;
    __half *pB1, *pB2, *pBl;
    cudaGetSymbolAddress((void**)&pxW, g_xW16);
    cudaGetSymbolAddress((void**)&psq, g_sq);
    cudaGetSymbolAddress((void**)&psk, g_sk);
    cudaGetSymbolAddress((void**)&pXf, g_Xf);
    cudaGetSymbolAddress((void**)&pHf, g_Hf);
    cudaGetSymbolAddress((void**)&pB1, g_B1);
    cudaGetSymbolAddress((void**)&pB2, g_B2);
    cudaGetSymbolAddress((void**)&pBl, g_Bl);

    cudaFuncSetAttribute(k_gemm_tc<false>, cudaFuncAttributeMaxDynamicSharedMemorySize, SMEM_TC);
    cudaFuncSetAttribute(k_gemm_tc<true>,  cudaFuncAttributeMaxDynamicSharedMemorySize, SMEM_TC);

    const int GT128 = (NN + 127) / 128;        // 391
    dim3 tc_grid(GT128, RR / 2);               // 2 relations per block
    const int agg_blocks = (NN * 32 + 255) / 256;
    const int EB = (EE + 255) / 256;

    // Order: prep zeroes cursor BEFORE convX's folded histogram.
    // k_gemm_tc (layer 1) stays the 4th launch -> ncu capture.
    k_prep<<<((2 * RR + 1) * 16384 + 255) / 256, 256>>>(W1, W2, Wl);   // 1 (+zero)
    k_convX<<<(NN * 16 + 255) / 256, 256>>>(x, pXf, tgtp);             // 2 (+hist/rank)
    k_scan_one<<<1, SCAN_T>>>();                                       // 3
    k_gemm_tc<false><<<tc_grid, 256, SMEM_TC>>>(pXf, pB1, pxW, nullptr,
                                                psq, psk, q1, k1, nullptr);  // 4
    k_fill<<<EB, 256>>>(srcp, tgtp, et);                               // 5

    k_agg<<<agg_blocks, 256>>>(pxW, psq, psk, b1, pHf);                // 6

    k_gemm_tc<false><<<tc_grid, 256, SMEM_TC>>>(pHf, pB2, pxW, nullptr,
                                                psq, psk, q2, k2, nullptr);  // 7
    k_agg<<<agg_blocks, 256>>>(pxW, psq, psk, b2, pHf);                // 8

    k_gemm_tc<true><<<dim3(GT128, 1), 256, SMEM_TC>>>(pHf, pBl, nullptr, out,
                                                      nullptr, nullptr, nullptr, nullptr, bl);  // 9
    (void)in_sizes; (void)n_in; (void)out_size;
}